// round 7
// baseline (speedup 1.0000x reference)
#include <cuda_runtime.h>
#include <math.h>

#define LCc 1024
#define LQq 512
#define NB  64
#define ND  256

__device__ float g_E[(size_t)NB * LCc * LQq];
__device__ float g_M[(size_t)NB * LQq * ND];
__device__ float g_sub0[NB * LCc];
__device__ float g_sub1[NB * LQq];
__device__ float g_rsum[NB * LCc];
__device__ float g_invrs[NB * LCc];
__device__ float g_csum2[NB * LQq];

__device__ __forceinline__ float f2tf(float f) {
    unsigned r; asm("cvt.rna.tf32.f32 %0, %1;" : "=r"(r) : "f"(f));
    return __uint_as_float(r);
}
__device__ __forceinline__ void mma8(float4& d,
        unsigned a0, unsigned a1, unsigned a2, unsigned a3,
        unsigned b0, unsigned b1) {
    asm volatile("mma.sync.aligned.m16n8k8.row.col.f32.tf32.tf32.f32 "
        "{%0,%1,%2,%3}, {%4,%5,%6,%7}, {%8,%9}, {%0,%1,%2,%3};"
        : "+f"(d.x), "+f"(d.y), "+f"(d.z), "+f"(d.w)
        : "r"(a0), "r"(a1), "r"(a2), "r"(a3), "r"(b0), "r"(b1));
}
__device__ __forceinline__ unsigned ldu(const float* p) { return __float_as_uint(*p); }

__global__ void k_init() {
    int i = blockIdx.x * blockDim.x + threadIdx.x;
    if (i < NB * LQq) g_csum2[i] = 0.f;
    if (i < NB * LCc) g_rsum[i] = 0.f;
}
__global__ void k_fin() {
    int i = blockIdx.x * blockDim.x + threadIdx.x;
    if (i < NB * LCc) g_invrs[i] = 1.0f / g_rsum[i];
}

__global__ __launch_bounds__(256) void k0_sub(const float* __restrict__ C,
                                              const float* __restrict__ Q,
                                              const float* __restrict__ w4C,
                                              const float* __restrict__ w4Q) {
    int gw   = (blockIdx.x * blockDim.x + threadIdx.x) >> 5;
    int lane = threadIdx.x & 31;
    const float* src; const float* w; float* dst;
    if (gw < NB * LCc) {
        src = C + (size_t)gw * ND; w = w4C;
        int c = gw / NB, b = gw % NB;
        dst = g_sub0 + b * LCc + c;
    } else {
        int r = gw - NB * LCc;
        if (r >= NB * LQq) return;
        src = Q + (size_t)r * ND; w = w4Q;
        int q = r / NB, b = r % NB;
        dst = g_sub1 + b * LQq + q;
    }
    float acc = 0.f;
    const float4* s4 = (const float4*)src;
    const float4* w4 = (const float4*)w;
#pragma unroll
    for (int j = 0; j < 2; ++j) {
        float4 a = s4[lane + 32 * j], ww = w4[lane + 32 * j];
        acc += a.x * ww.x + a.y * ww.y + a.z * ww.z + a.w * ww.w;
    }
#pragma unroll
    for (int off = 16; off; off >>= 1) acc += __shfl_xor_sync(0xffffffffu, acc, off);
    if (lane == 0) *dst = acc;
}

// ---- k1: E = exp(C @ (wml*Q)^T + sub0 + sub1 + bias); fused row/col sums ----
__global__ __launch_bounds__(256) void k1_scores(const float* __restrict__ C,
                                                 const float* __restrict__ Q,
                                                 const float* __restrict__ w4mlu,
                                                 const float* __restrict__ bias) {
    __shared__ float As[2][16][136];
    __shared__ float Bs[2][16][136];
    __shared__ float wml[ND];
    const int b = blockIdx.z, c0 = blockIdx.y * 128, q0 = blockIdx.x * 128;
    const int tid = threadIdx.x;
    wml[tid] = w4mlu[tid];
    const int lane = tid & 31, w = tid >> 5;
    const int g = lane >> 2, t = lane & 3;
    const int mbase = (w >> 2) * 64, nbase = (w & 3) * 32;
    const int lrow = tid & 127, lks = (tid >> 7) * 8;
    const float* Ag = C + (size_t)(c0 + lrow) * (NB * ND) + (size_t)b * ND + lks;
    const float* Bg = Q + (size_t)(q0 + lrow) * (NB * ND) + (size_t)b * ND + lks;
    float4 pa0 = *(const float4*)Ag, pa1 = *(const float4*)(Ag + 4);
    float4 pb0 = *(const float4*)Bg, pb1 = *(const float4*)(Bg + 4);
    float4 acc[4][4] = {};
    __syncthreads();   // wml ready
    {   // stage chunk 0 -> buf 0
        As[0][lks + 0][lrow] = f2tf(pa0.x); As[0][lks + 1][lrow] = f2tf(pa0.y);
        As[0][lks + 2][lrow] = f2tf(pa0.z); As[0][lks + 3][lrow] = f2tf(pa0.w);
        As[0][lks + 4][lrow] = f2tf(pa1.x); As[0][lks + 5][lrow] = f2tf(pa1.y);
        As[0][lks + 6][lrow] = f2tf(pa1.z); As[0][lks + 7][lrow] = f2tf(pa1.w);
        Bs[0][lks + 0][lrow] = f2tf(pb0.x * wml[lks + 0]);
        Bs[0][lks + 1][lrow] = f2tf(pb0.y * wml[lks + 1]);
        Bs[0][lks + 2][lrow] = f2tf(pb0.z * wml[lks + 2]);
        Bs[0][lks + 3][lrow] = f2tf(pb0.w * wml[lks + 3]);
        Bs[0][lks + 4][lrow] = f2tf(pb1.x * wml[lks + 4]);
        Bs[0][lks + 5][lrow] = f2tf(pb1.y * wml[lks + 5]);
        Bs[0][lks + 6][lrow] = f2tf(pb1.z * wml[lks + 6]);
        Bs[0][lks + 7][lrow] = f2tf(pb1.w * wml[lks + 7]);
    }
    __syncthreads();
    int p = 0;
    for (int k0 = 0; k0 < ND; k0 += 16) {
        const bool nxt = (k0 + 16) < ND;
        if (nxt) {
            pa0 = *(const float4*)(Ag + k0 + 16); pa1 = *(const float4*)(Ag + k0 + 20);
            pb0 = *(const float4*)(Bg + k0 + 16); pb1 = *(const float4*)(Bg + k0 + 20);
        }
#pragma unroll
        for (int kk = 0; kk < 16; kk += 8) {
            unsigned af[4][4], bf[4][2];
#pragma unroll
            for (int mi = 0; mi < 4; ++mi) {
                int m = mbase + mi * 16 + g;
                af[mi][0] = ldu(&As[p][kk + t][m]);     af[mi][1] = ldu(&As[p][kk + t][m + 8]);
                af[mi][2] = ldu(&As[p][kk + t + 4][m]); af[mi][3] = ldu(&As[p][kk + t + 4][m + 8]);
            }
#pragma unroll
            for (int ni = 0; ni < 4; ++ni) {
                int n = nbase + ni * 8 + g;
                bf[ni][0] = ldu(&Bs[p][kk + t][n]); bf[ni][1] = ldu(&Bs[p][kk + t + 4][n]);
            }
#pragma unroll
            for (int mi = 0; mi < 4; ++mi)
#pragma unroll
                for (int ni = 0; ni < 4; ++ni)
                    mma8(acc[mi][ni], af[mi][0], af[mi][1], af[mi][2], af[mi][3],
                         bf[ni][0], bf[ni][1]);
        }
        if (nxt) {
            const int kb = k0 + 16, q2 = p ^ 1;
            As[q2][lks + 0][lrow] = f2tf(pa0.x); As[q2][lks + 1][lrow] = f2tf(pa0.y);
            As[q2][lks + 2][lrow] = f2tf(pa0.z); As[q2][lks + 3][lrow] = f2tf(pa0.w);
            As[q2][lks + 4][lrow] = f2tf(pa1.x); As[q2][lks + 5][lrow] = f2tf(pa1.y);
            As[q2][lks + 6][lrow] = f2tf(pa1.z); As[q2][lks + 7][lrow] = f2tf(pa1.w);
            Bs[q2][lks + 0][lrow] = f2tf(pb0.x * wml[kb + lks + 0]);
            Bs[q2][lks + 1][lrow] = f2tf(pb0.y * wml[kb + lks + 1]);
            Bs[q2][lks + 2][lrow] = f2tf(pb0.z * wml[kb + lks + 2]);
            Bs[q2][lks + 3][lrow] = f2tf(pb0.w * wml[kb + lks + 3]);
            Bs[q2][lks + 4][lrow] = f2tf(pb1.x * wml[kb + lks + 4]);
            Bs[q2][lks + 5][lrow] = f2tf(pb1.y * wml[kb + lks + 5]);
            Bs[q2][lks + 6][lrow] = f2tf(pb1.z * wml[kb + lks + 6]);
            Bs[q2][lks + 7][lrow] = f2tf(pb1.w * wml[kb + lks + 7]);
        }
        __syncthreads();
        p ^= 1;
    }
    const float bv = bias[0];
    float s1x[4], s1y[4];
#pragma unroll
    for (int ni = 0; ni < 4; ++ni) {
        int q = q0 + nbase + ni * 8 + 2 * t;
        s1x[ni] = g_sub1[b * LQq + q];
        s1y[ni] = g_sub1[b * LQq + q + 1];
    }
    float rs0[4] = {}, rs1[4] = {}, ccx[4] = {}, ccy[4] = {};
#pragma unroll
    for (int mi = 0; mi < 4; ++mi) {
        int cA = c0 + mbase + mi * 16 + g;
        float s0a = g_sub0[b * LCc + cA] + bv;
        float s0b = g_sub0[b * LCc + cA + 8] + bv;
        float* r0 = g_E + ((size_t)b * LCc + cA) * LQq + q0;
        float* r1 = r0 + 8 * LQq;
#pragma unroll
        for (int ni = 0; ni < 4; ++ni) {
            int q = nbase + ni * 8 + 2 * t;
            float2 e0 = {expf(acc[mi][ni].x + s0a + s1x[ni]),
                         expf(acc[mi][ni].y + s0a + s1y[ni])};
            float2 e1 = {expf(acc[mi][ni].z + s0b + s1x[ni]),
                         expf(acc[mi][ni].w + s0b + s1y[ni])};
            *(float2*)(r0 + q) = e0;
            *(float2*)(r1 + q) = e1;
            rs0[mi] += e0.x + e0.y; rs1[mi] += e1.x + e1.y;
            ccx[ni] += e0.x + e1.x; ccy[ni] += e0.y + e1.y;
        }
    }
#pragma unroll
    for (int mi = 0; mi < 4; ++mi) {   // reduce over t (lane bits 0,1)
        float a = rs0[mi], c2 = rs1[mi];
        a  += __shfl_xor_sync(0xffffffffu, a, 1);  a  += __shfl_xor_sync(0xffffffffu, a, 2);
        c2 += __shfl_xor_sync(0xffffffffu, c2, 1); c2 += __shfl_xor_sync(0xffffffffu, c2, 2);
        if (t == 0) {
            int cA = c0 + mbase + mi * 16 + g;
            atomicAdd(&g_rsum[b * LCc + cA], a);
            atomicAdd(&g_rsum[b * LCc + cA + 8], c2);
        }
    }
#pragma unroll
    for (int ni = 0; ni < 4; ++ni) {   // reduce over g (lane bits 2,3,4)
        float x = ccx[ni], y = ccy[ni];
        x += __shfl_xor_sync(0xffffffffu, x, 4);  y += __shfl_xor_sync(0xffffffffu, y, 4);
        x += __shfl_xor_sync(0xffffffffu, x, 8);  y += __shfl_xor_sync(0xffffffffu, y, 8);
        x += __shfl_xor_sync(0xffffffffu, x, 16); y += __shfl_xor_sync(0xffffffffu, y, 16);
        if (g == 0) {
            int q = q0 + nbase + ni * 8 + 2 * t;
            atomicAdd(&g_csum2[b * LQq + q], x);
            atomicAdd(&g_csum2[b * LQq + q + 1], y);
        }
    }
}

// ---- k4: M = E^T @ C / colsum ----
__global__ __launch_bounds__(256) void k4_M(const float* __restrict__ C) {
    __shared__ float As[2][16][136];
    __shared__ float Bs[2][16][136];
    const int b = blockIdx.z, q0 = blockIdx.y * 128, d0 = blockIdx.x * 128;
    const int tid = threadIdx.x;
    const int lane = tid & 31, w = tid >> 5;
    const int g = lane >> 2, t = lane & 3;
    const int mbase = (w >> 2) * 64, nbase = (w & 3) * 32;
    const int l4 = (lane & 31) * 4 % 128;
    const int crr = tid >> 5;
    const float* Ag = g_E + ((size_t)b * LCc + crr) * LQq + q0 + l4;
    const float* Bg = C + (size_t)crr * (NB * ND) + (size_t)b * ND + d0 + l4;
    float4 pa0 = *(const float4*)Ag;
    float4 pa1 = *(const float4*)(Ag + (size_t)8 * LQq);
    float4 pb0 = *(const float4*)Bg;
    float4 pb1 = *(const float4*)(Bg + (size_t)8 * (NB * ND));
    float4 acc[4][4] = {};
    {
        *(float4*)&As[0][crr][l4]     = make_float4(f2tf(pa0.x), f2tf(pa0.y), f2tf(pa0.z), f2tf(pa0.w));
        *(float4*)&As[0][crr + 8][l4] = make_float4(f2tf(pa1.x), f2tf(pa1.y), f2tf(pa1.z), f2tf(pa1.w));
        *(float4*)&Bs[0][crr][l4]     = make_float4(f2tf(pb0.x), f2tf(pb0.y), f2tf(pb0.z), f2tf(pb0.w));
        *(float4*)&Bs[0][crr + 8][l4] = make_float4(f2tf(pb1.x), f2tf(pb1.y), f2tf(pb1.z), f2tf(pb1.w));
    }
    __syncthreads();
    int p = 0;
    for (int cb = 0; cb < LCc; cb += 16) {
        const bool nxt = (cb + 16) < LCc;
        if (nxt) {
            pa0 = *(const float4*)(Ag + (size_t)(cb + 16) * LQq);
            pa1 = *(const float4*)(Ag + (size_t)(cb + 24) * LQq);
            pb0 = *(const float4*)(Bg + (size_t)(cb + 16) * (NB * ND));
            pb1 = *(const float4*)(Bg + (size_t)(cb + 24) * (NB * ND));
        }
#pragma unroll
        for (int kk = 0; kk < 16; kk += 8) {
            unsigned af[4][4], bf[4][2];
#pragma unroll
            for (int mi = 0; mi < 4; ++mi) {
                int m = mbase + mi * 16 + g;
                af[mi][0] = ldu(&As[p][kk + t][m]);     af[mi][1] = ldu(&As[p][kk + t][m + 8]);
                af[mi][2] = ldu(&As[p][kk + t + 4][m]); af[mi][3] = ldu(&As[p][kk + t + 4][m + 8]);
            }
#pragma unroll
            for (int ni = 0; ni < 4; ++ni) {
                int n = nbase + ni * 8 + g;
                bf[ni][0] = ldu(&Bs[p][kk + t][n]); bf[ni][1] = ldu(&Bs[p][kk + t + 4][n]);
            }
#pragma unroll
            for (int mi = 0; mi < 4; ++mi)
#pragma unroll
                for (int ni = 0; ni < 4; ++ni)
                    mma8(acc[mi][ni], af[mi][0], af[mi][1], af[mi][2], af[mi][3],
                         bf[ni][0], bf[ni][1]);
        }
        if (nxt) {
            const int q2 = p ^ 1;
            *(float4*)&As[q2][crr][l4]     = make_float4(f2tf(pa0.x), f2tf(pa0.y), f2tf(pa0.z), f2tf(pa0.w));
            *(float4*)&As[q2][crr + 8][l4] = make_float4(f2tf(pa1.x), f2tf(pa1.y), f2tf(pa1.z), f2tf(pa1.w));
            *(float4*)&Bs[q2][crr][l4]     = make_float4(f2tf(pb0.x), f2tf(pb0.y), f2tf(pb0.z), f2tf(pb0.w));
            *(float4*)&Bs[q2][crr + 8][l4] = make_float4(f2tf(pb1.x), f2tf(pb1.y), f2tf(pb1.z), f2tf(pb1.w));
        }
        __syncthreads();
        p ^= 1;
    }
#pragma unroll
    for (int mi = 0; mi < 4; ++mi) {
        int qA = q0 + mbase + mi * 16 + g;
        float i0 = 1.0f / g_csum2[b * LQq + qA];
        float i1 = 1.0f / g_csum2[b * LQq + qA + 8];
        float* r0 = g_M + ((size_t)b * LQq + qA) * ND + d0;
        float* r1 = r0 + 8 * ND;
#pragma unroll
        for (int ni = 0; ni < 4; ++ni) {
            int d = nbase + ni * 8 + 2 * t;
            *(float2*)(r0 + d) = make_float2(acc[mi][ni].x * i0, acc[mi][ni].y * i0);
            *(float2*)(r1 + d) = make_float2(acc[mi][ni].z * i1, acc[mi][ni].w * i1);
        }
    }
}

// ---- k5: A = S1@Q, B_ = S1@M, fused transposed-concat ----
__global__ __launch_bounds__(256) void k5_out(const float* __restrict__ C,
                                              const float* __restrict__ Q,
                                              float* __restrict__ out) {
    __shared__ __align__(16) float smem[8960];
    float (*As)[16][136] = (float(*)[16][136])smem;            // 2*2176
    float (*Bq)[16][72]  = (float(*)[16][72])(smem + 4352);    // 2*1152
    float (*Bm)[16][72]  = (float(*)[16][72])(smem + 6656);    // 2*1152
    float (*Cs)[65]      = (float(*)[65])smem;                 // epi
    float (*Tr)[69]      = (float(*)[69])(smem + 4160);        // epi
    const int b = blockIdx.z, c0 = blockIdx.y * 128, d0 = blockIdx.x * 64;
    const int tid = threadIdx.x;
    const int lane = tid & 31, w = tid >> 5;
    const int g = lane >> 2, t = lane & 3;
    const int wr = w >> 1, wc = w & 1;
    const int mbase = wr * 32, nbase = wc * 32;
    const int lrow = tid & 127, lks = (tid >> 7) * 8;
    const int qr = tid >> 4, dl = (tid & 15) * 4;
    const float* Ag = g_E + ((size_t)b * LCc + c0 + lrow) * LQq + lks;
    const float* Qg = Q + (size_t)b * ND + d0 + dl;
    const float* Mg = g_M + (size_t)b * LQq * ND + d0 + dl;
    float4 pa0 = *(const float4*)Ag, pa1 = *(const float4*)(Ag + 4);
    float4 pq = *(const float4*)(Qg + (size_t)qr * (NB * ND));
    float4 pm = *(const float4*)(Mg + (size_t)qr * ND);
    float4 accA[2][4] = {}, accB[2][4] = {};
    {
        As[0][lks + 0][lrow] = f2tf(pa0.x); As[0][lks + 1][lrow] = f2tf(pa0.y);
        As[0][lks + 2][lrow] = f2tf(pa0.z); As[0][lks + 3][lrow] = f2tf(pa0.w);
        As[0][lks + 4][lrow] = f2tf(pa1.x); As[0][lks + 5][lrow] = f2tf(pa1.y);
        As[0][lks + 6][lrow] = f2tf(pa1.z); As[0][lks + 7][lrow] = f2tf(pa1.w);
        *(float4*)&Bq[0][qr][dl] = make_float4(f2tf(pq.x), f2tf(pq.y), f2tf(pq.z), f2tf(pq.w));
        *(float4*)&Bm[0][qr][dl] = make_float4(f2tf(pm.x), f2tf(pm.y), f2tf(pm.z), f2tf(pm.w));
    }
    __syncthreads();
    int p = 0;
    for (int k0 = 0; k0 < LQq; k0 += 16) {
        const bool nxt = (k0 + 16) < LQq;
        if (nxt) {
            pa0 = *(const float4*)(Ag + k0 + 16); pa1 = *(const float4*)(Ag + k0 + 20);
            pq = *(const float4*)(Qg + (size_t)(k0 + 16 + qr) * (NB * ND));
            pm = *(const float4*)(Mg + (size_t)(k0 + 16 + qr) * ND);
        }
#pragma unroll
        for (int kk = 0; kk < 16; kk += 8) {
            unsigned af[2][4], qf[4][2], mf[4][2];
#pragma unroll
            for (int mi = 0; mi < 2; ++mi) {
                int m = mbase + mi * 16 + g;
                af[mi][0] = ldu(&As[p][kk + t][m]);     af[mi][1] = ldu(&As[p][kk + t][m + 8]);
                af[mi][2] = ldu(&As[p][kk + t + 4][m]); af[mi][3] = ldu(&As[p][kk + t + 4][m + 8]);
            }
#pragma unroll
            for (int ni = 0; ni < 4; ++ni) {
                int n = nbase + ni * 8 + g;
                qf[ni][0] = ldu(&Bq[p][kk + t][n]); qf[ni][1] = ldu(&Bq[p][kk + t + 4][n]);
                mf[ni][0] = ldu(&Bm[p][kk + t][n]); mf[ni][1] = ldu(&Bm[p][kk + t + 4][n]);
            }
#pragma unroll
            for (int mi = 0; mi < 2; ++mi)
#pragma unroll
                for (int ni = 0; ni < 4; ++ni) {
                    mma8(accA[mi][ni], af[mi][0], af[mi][1], af[mi][2], af[mi][3],
                         qf[ni][0], qf[ni][1]);
                    mma8(accB[mi][ni], af[mi][0], af[mi][1], af[mi][2], af[mi][3],
                         mf[ni][0], mf[ni][1]);
                }
        }
        if (nxt) {
            const int q2 = p ^ 1;
            As[q2][lks + 0][lrow] = f2tf(pa0.x); As[q2][lks + 1][lrow] = f2tf(pa0.y);
            As[q2][lks + 2][lrow] = f2tf(pa0.z); As[q2][lks + 3][lrow] = f2tf(pa0.w);
            As[q2][lks + 4][lrow] = f2tf(pa1.x); As[q2][lks + 5][lrow] = f2tf(pa1.y);
            As[q2][lks + 6][lrow] = f2tf(pa1.z); As[q2][lks + 7][lrow] = f2tf(pa1.w);
            *(float4*)&Bq[q2][qr][dl] = make_float4(f2tf(pq.x), f2tf(pq.y), f2tf(pq.z), f2tf(pq.w));
            *(float4*)&Bm[q2][qr][dl] = make_float4(f2tf(pm.x), f2tf(pm.y), f2tf(pm.z), f2tf(pm.w));
        }
        __syncthreads();
        p ^= 1;
    }
#pragma unroll
    for (int mi = 0; mi < 2; ++mi) {
        int cA = c0 + mbase + mi * 16 + g;
        float i0 = g_invrs[b * LCc + cA];
        float i1 = g_invrs[b * LCc + cA + 8];
#pragma unroll
        for (int ni = 0; ni < 4; ++ni) {
            accA[mi][ni].x *= i0; accA[mi][ni].y *= i0;
            accA[mi][ni].z *= i1; accA[mi][ni].w *= i1;
            accB[mi][ni].x *= i0; accB[mi][ni].y *= i0;
            accB[mi][ni].z *= i1; accB[mi][ni].w *= i1;
        }
    }
    const int cl = tid & 63, dseg = (tid >> 6) * 16;
    const int cr = tid & 63, db = tid >> 6;
    const size_t ob = (size_t)b * (4 * ND) * LCc;
    for (int h = 0; h < 2; ++h) {
        __syncthreads();
        {
            const float* Cg = C + (size_t)(c0 + h * 64 + cl) * (NB * ND) + (size_t)b * ND + d0 + dseg;
#pragma unroll
            for (int dd = 0; dd < 16; dd += 4) {
                float4 cv = *(const float4*)(Cg + dd);
                Cs[dseg + dd + 0][cl] = cv.x; Cs[dseg + dd + 1][cl] = cv.y;
                Cs[dseg + dd + 2][cl] = cv.z; Cs[dseg + dd + 3][cl] = cv.w;
            }
        }
        if ((w >> 2) == h) {
#pragma unroll
            for (int mi = 0; mi < 2; ++mi) {
                int clh = (wr & 1) * 32 + mi * 16 + g;
#pragma unroll
                for (int ni = 0; ni < 4; ++ni) {
                    int d = nbase + ni * 8 + 2 * t;
                    Tr[clh][d] = accA[mi][ni].x;     Tr[clh][d + 1] = accA[mi][ni].y;
                    Tr[clh + 8][d] = accA[mi][ni].z; Tr[clh + 8][d + 1] = accA[mi][ni].w;
                }
            }
        }
        __syncthreads();
#pragma unroll
        for (int rr = 0; rr < 16; ++rr) {
            int dr = db + rr * 4;
            float cval = Cs[dr][cr];
            float aval = Tr[cr][dr];
            size_t col = (size_t)(c0 + h * 64 + cr);
            out[ob + (size_t)(d0 + dr) * LCc + col]          = cval;
            out[ob + (size_t)(ND + d0 + dr) * LCc + col]     = aval;
            out[ob + (size_t)(2 * ND + d0 + dr) * LCc + col] = cval * aval;
        }
        __syncthreads();
        if ((w >> 2) == h) {
#pragma unroll
            for (int mi = 0; mi < 2; ++mi) {
                int clh = (wr & 1) * 32 + mi * 16 + g;
#pragma unroll
                for (int ni = 0; ni < 4; ++ni) {
                    int d = nbase + ni * 8 + 2 * t;
                    Tr[clh][d] = accB[mi][ni].x;     Tr[clh][d + 1] = accB[mi][ni].y;
                    Tr[clh + 8][d] = accB[mi][ni].z; Tr[clh + 8][d + 1] = accB[mi][ni].w;
                }
            }
        }
        __syncthreads();
#pragma unroll
        for (int rr = 0; rr < 16; ++rr) {
            int dr = db + rr * 4;
            out[ob + (size_t)(3 * ND + d0 + dr) * LCc + (size_t)(c0 + h * 64 + cr)] =
                Cs[dr][cr] * Tr[cr][dr];
        }
    }
}

extern "C" void kernel_launch(void* const* d_in, const int* in_sizes, int n_in,
                              void* d_out, int out_size) {
    const float* C     = (const float*)d_in[0];
    const float* Q     = (const float*)d_in[1];
    const float* w4C   = (const float*)d_in[2];
    const float* w4Q   = (const float*)d_in[3];
    const float* w4mlu = (const float*)d_in[4];
    const float* bias  = (const float*)d_in[5];
    float* out = (float*)d_out;

    k_init<<<(NB * LCc + 255) / 256, 256>>>();
    k0_sub<<<(NB * LCc + NB * LQq) / 8, 256>>>(C, Q, w4C, w4Q);
    k1_scores<<<dim3(LQq / 128, LCc / 128, NB), 256>>>(C, Q, w4mlu, bias);
    k_fin<<<(NB * LCc + 255) / 256, 256>>>();
    k4_M<<<dim3(ND / 128, LQq / 128, NB), 256>>>(C);
    k5_out<<<dim3(ND / 64, LCc / 128, NB), 256>>>(C, Q, out);
}

// round 9
// speedup vs baseline: 1.5300x; 1.5300x over previous
#include <cuda_runtime.h>
#include <math.h>

#define LCc 1024
#define LQq 512
#define NB  64
#define ND  256

typedef unsigned int u32;

__device__ float g_E[(size_t)NB * LCc * LQq];     // tf32-rounded exp(S)
__device__ float g_M[(size_t)NB * LQq * ND];      // tf32-rounded M
__device__ float g_Ctf[(size_t)LCc * NB * ND];    // tf32-rounded C
__device__ float g_Qtf[(size_t)LQq * NB * ND];    // tf32-rounded Q
__device__ float g_Qw[(size_t)LQq * NB * ND];     // tf32-rounded Q*wml
__device__ float g_sub0[NB * LCc];
__device__ float g_sub1[NB * LQq];
__device__ float g_rsum[NB * LCc];
__device__ float g_invrs[NB * LCc];
__device__ float g_csum2[NB * LQq];

// ---------------- helpers -----------------------------------------------------
__device__ __forceinline__ float f2tf(float f) {
    u32 r; asm("cvt.rna.tf32.f32 %0, %1;" : "=r"(r) : "f"(f));
    return __uint_as_float(r);
}
__device__ __forceinline__ void mma8(float4& d,
        u32 a0, u32 a1, u32 a2, u32 a3, u32 b0, u32 b1) {
    asm volatile("mma.sync.aligned.m16n8k8.row.col.f32.tf32.tf32.f32 "
        "{%0,%1,%2,%3}, {%4,%5,%6,%7}, {%8,%9}, {%0,%1,%2,%3};"
        : "+f"(d.x), "+f"(d.y), "+f"(d.z), "+f"(d.w)
        : "r"(a0), "r"(a1), "r"(a2), "r"(a3), "r"(b0), "r"(b1));
}
__device__ __forceinline__ u32 ldu(const float* p) { return __float_as_uint(*p); }
__device__ __forceinline__ u32 smem_u32(const void* p) {
    u32 a; asm("{ .reg .u64 t; cvta.to.shared.u64 t, %1; cvt.u32.u64 %0, t; }"
               : "=r"(a) : "l"(p));
    return a;
}
__device__ __forceinline__ void cpa16(u32 dst, const float* src) {
    asm volatile("cp.async.cg.shared.global [%0], [%1], 16;" :: "r"(dst), "l"(src) : "memory");
}
__device__ __forceinline__ void cpa_commit() {
    asm volatile("cp.async.commit_group;" ::: "memory");
}
template<int N>
__device__ __forceinline__ void cpa_wait() {
    asm volatile("cp.async.wait_group %0;" :: "n"(N) : "memory");
}

// ---------------- small kernels ------------------------------------------------
__global__ void k_init() {
    int i = blockIdx.x * blockDim.x + threadIdx.x;
    if (i < NB * LQq) g_csum2[i] = 0.f;
    if (i < NB * LCc) g_rsum[i] = 0.f;
}
__global__ void k_fin() {
    int i = blockIdx.x * blockDim.x + threadIdx.x;
    if (i < NB * LCc) g_invrs[i] = 1.0f / g_rsum[i];
}

__global__ __launch_bounds__(256) void k0_sub(const float* __restrict__ C,
                                              const float* __restrict__ Q,
                                              const float* __restrict__ w4C,
                                              const float* __restrict__ w4Q) {
    int gw   = (blockIdx.x * blockDim.x + threadIdx.x) >> 5;
    int lane = threadIdx.x & 31;
    const float* src; const float* w; float* dst;
    if (gw < NB * LCc) {
        src = C + (size_t)gw * ND; w = w4C;
        int c = gw / NB, b = gw % NB;
        dst = g_sub0 + b * LCc + c;
    } else {
        int r = gw - NB * LCc;
        if (r >= NB * LQq) return;
        src = Q + (size_t)r * ND; w = w4Q;
        int q = r / NB, b = r % NB;
        dst = g_sub1 + b * LQq + q;
    }
    float acc = 0.f;
    const float4* s4 = (const float4*)src;
    const float4* w4 = (const float4*)w;
#pragma unroll
    for (int j = 0; j < 2; ++j) {
        float4 a = s4[lane + 32 * j], ww = w4[lane + 32 * j];
        acc += a.x * ww.x + a.y * ww.y + a.z * ww.z + a.w * ww.w;
    }
#pragma unroll
    for (int off = 16; off; off >>= 1) acc += __shfl_xor_sync(0xffffffffu, acc, off);
    if (lane == 0) *dst = acc;
}

// pre-round Q -> g_Qtf, and Q*wml -> g_Qw
__global__ __launch_bounds__(256) void k0q(const float* __restrict__ Q,
                                           const float* __restrict__ wml) {
    int i = blockIdx.x * blockDim.x + threadIdx.x;
    if (i >= LQq * NB * ND / 4) return;
    float4 v = ((const float4*)Q)[i];
    float4 ww = ((const float4*)wml)[i & 63];
    ((float4*)g_Qtf)[i] = make_float4(f2tf(v.x), f2tf(v.y), f2tf(v.z), f2tf(v.w));
    ((float4*)g_Qw)[i]  = make_float4(f2tf(v.x * ww.x), f2tf(v.y * ww.y),
                                      f2tf(v.z * ww.z), f2tf(v.w * ww.w));
}
// pre-round C -> g_Ctf
__global__ __launch_bounds__(256) void k0c(const float* __restrict__ C) {
    int i = blockIdx.x * blockDim.x + threadIdx.x;
    if (i >= LCc * NB * ND / 4) return;
    float4 v = ((const float4*)C)[i];
    ((float4*)g_Ctf)[i] = make_float4(f2tf(v.x), f2tf(v.y), f2tf(v.z), f2tf(v.w));
}

// ---- k1: E = rna(exp(Ctf @ Qw^T + sub0 + sub1 + bias)); fused row/col sums ----
// CTA 128(c) x 128(q); A,B tiles [row][k] stride 20, cp.async double-buffered
__global__ __launch_bounds__(256, 2) void k1_scores(const float* __restrict__ bias) {
    __shared__ float As[2][128][20];
    __shared__ float Bs[2][128][20];
    const int tid = threadIdx.x, lane = tid & 31, w = tid >> 5;
    const int g = lane >> 2, t = lane & 3;
    const int b = blockIdx.z, c0 = blockIdx.y * 128, q0 = blockIdx.x * 128;
    const int mbase = (w >> 2) * 64, nbase = (w & 3) * 32;
    const int rowA = tid >> 1, hf = (tid & 1) * 8;
    const float* Ag = g_Ctf + (size_t)(c0 + rowA) * (NB * ND) + (size_t)b * ND + hf;
    const float* Bg = g_Qw  + (size_t)(q0 + rowA) * (NB * ND) + (size_t)b * ND + hf;
    const u32 Ad = smem_u32(&As[0][rowA][hf]);
    const u32 Bd = smem_u32(&Bs[0][rowA][hf]);
    cpa16(Ad, Ag); cpa16(Ad + 16, Ag + 4);
    cpa16(Bd, Bg); cpa16(Bd + 16, Bg + 4);
    cpa_commit();
    float4 acc[4][4] = {};
    for (int ch = 0; ch < 16; ++ch) {
        const int p = ch & 1;
        if (ch < 15) {
            const int ko = (ch + 1) * 16;
            const u32 off = (u32)((p ^ 1) * 10240);
            cpa16(Ad + off, Ag + ko); cpa16(Ad + off + 16, Ag + ko + 4);
            cpa16(Bd + off, Bg + ko); cpa16(Bd + off + 16, Bg + ko + 4);
            cpa_commit();
            cpa_wait<1>();
        } else cpa_wait<0>();
        __syncthreads();
#pragma unroll
        for (int kk = 0; kk < 16; kk += 8) {
            u32 af[4][4], bf[4][2];
#pragma unroll
            for (int mi = 0; mi < 4; ++mi) {
                int m = mbase + mi * 16 + g;
                af[mi][0] = ldu(&As[p][m][kk + t]);
                af[mi][1] = ldu(&As[p][m + 8][kk + t]);
                af[mi][2] = ldu(&As[p][m][kk + t + 4]);
                af[mi][3] = ldu(&As[p][m + 8][kk + t + 4]);
            }
#pragma unroll
            for (int ni = 0; ni < 4; ++ni) {
                int n = nbase + ni * 8 + g;
                bf[ni][0] = ldu(&Bs[p][n][kk + t]);
                bf[ni][1] = ldu(&Bs[p][n][kk + t + 4]);
            }
#pragma unroll
            for (int mi = 0; mi < 4; ++mi)
#pragma unroll
                for (int ni = 0; ni < 4; ++ni)
                    mma8(acc[mi][ni], af[mi][0], af[mi][1], af[mi][2], af[mi][3],
                         bf[ni][0], bf[ni][1]);
        }
        __syncthreads();
    }
    const float bv = bias[0];
    float s1x[4], s1y[4];
#pragma unroll
    for (int ni = 0; ni < 4; ++ni) {
        int q = q0 + nbase + ni * 8 + 2 * t;
        s1x[ni] = g_sub1[b * LQq + q];
        s1y[ni] = g_sub1[b * LQq + q + 1];
    }
    float rs0[4] = {}, rs1[4] = {}, ccx[4] = {}, ccy[4] = {};
#pragma unroll
    for (int mi = 0; mi < 4; ++mi) {
        int cA = c0 + mbase + mi * 16 + g;
        float s0a = g_sub0[b * LCc + cA] + bv;
        float s0b = g_sub0[b * LCc + cA + 8] + bv;
        float* r0 = g_E + ((size_t)b * LCc + cA) * LQq + q0;
        float* r1 = r0 + 8 * LQq;
#pragma unroll
        for (int ni = 0; ni < 4; ++ni) {
            int q = nbase + ni * 8 + 2 * t;
            float2 e0 = {f2tf(expf(acc[mi][ni].x + s0a + s1x[ni])),
                         f2tf(expf(acc[mi][ni].y + s0a + s1y[ni]))};
            float2 e1 = {f2tf(expf(acc[mi][ni].z + s0b + s1x[ni])),
                         f2tf(expf(acc[mi][ni].w + s0b + s1y[ni]))};
            *(float2*)(r0 + q) = e0;
            *(float2*)(r1 + q) = e1;
            rs0[mi] += e0.x + e0.y; rs1[mi] += e1.x + e1.y;
            ccx[ni] += e0.x + e1.x; ccy[ni] += e0.y + e1.y;
        }
    }
#pragma unroll
    for (int mi = 0; mi < 4; ++mi) {
        float a = rs0[mi], c2 = rs1[mi];
        a  += __shfl_xor_sync(0xffffffffu, a, 1);  a  += __shfl_xor_sync(0xffffffffu, a, 2);
        c2 += __shfl_xor_sync(0xffffffffu, c2, 1); c2 += __shfl_xor_sync(0xffffffffu, c2, 2);
        if (t == 0) {
            int cA = c0 + mbase + mi * 16 + g;
            atomicAdd(&g_rsum[b * LCc + cA], a);
            atomicAdd(&g_rsum[b * LCc + cA + 8], c2);
        }
    }
#pragma unroll
    for (int ni = 0; ni < 4; ++ni) {
        float x = ccx[ni], y = ccy[ni];
        x += __shfl_xor_sync(0xffffffffu, x, 4);  y += __shfl_xor_sync(0xffffffffu, y, 4);
        x += __shfl_xor_sync(0xffffffffu, x, 8);  y += __shfl_xor_sync(0xffffffffu, y, 8);
        x += __shfl_xor_sync(0xffffffffu, x, 16); y += __shfl_xor_sync(0xffffffffu, y, 16);
        if (g == 0) {
            int q = q0 + nbase + ni * 8 + 2 * t;
            atomicAdd(&g_csum2[b * LQq + q], x);
            atomicAdd(&g_csum2[b * LQq + q + 1], y);
        }
    }
}

// ---- k4: M = rna(E^T @ Ctf / colsum); tiles [k][row] stride 136, cp.async ------
__global__ __launch_bounds__(256, 2) void k4_M() {
    __shared__ float As[2][16][136];
    __shared__ float Bs[2][16][136];
    const int b = blockIdx.z, q0 = blockIdx.y * 128, d0 = blockIdx.x * 128;
    const int tid = threadIdx.x, lane = tid & 31, w = tid >> 5;
    const int g = lane >> 2, t = lane & 3;
    const int mbase = (w >> 2) * 64, nbase = (w & 3) * 32;
    const int crr = tid >> 4, seg = (tid & 15) * 8;
    const float* Ag = g_E + ((size_t)b * LCc + crr) * LQq + q0 + seg;
    const float* Bg = g_Ctf + (size_t)crr * (NB * ND) + (size_t)b * ND + d0 + seg;
    const u32 Ad = smem_u32(&As[0][crr][seg]);
    const u32 Bd = smem_u32(&Bs[0][crr][seg]);
    cpa16(Ad, Ag); cpa16(Ad + 16, Ag + 4);
    cpa16(Bd, Bg); cpa16(Bd + 16, Bg + 4);
    cpa_commit();
    float4 acc[4][4] = {};
    for (int ch = 0; ch < 64; ++ch) {
        const int p = ch & 1;
        if (ch < 63) {
            const size_t ca = (size_t)(ch + 1) * 16;
            const u32 off = (u32)((p ^ 1) * 8704);
            cpa16(Ad + off, Ag + ca * LQq); cpa16(Ad + off + 16, Ag + ca * LQq + 4);
            cpa16(Bd + off, Bg + ca * (NB * ND)); cpa16(Bd + off + 16, Bg + ca * (NB * ND) + 4);
            cpa_commit();
            cpa_wait<1>();
        } else cpa_wait<0>();
        __syncthreads();
#pragma unroll
        for (int kk = 0; kk < 16; kk += 8) {
            u32 af[4][4], bf[4][2];
#pragma unroll
            for (int mi = 0; mi < 4; ++mi) {
                int m = mbase + mi * 16 + g;
                af[mi][0] = ldu(&As[p][kk + t][m]);     af[mi][1] = ldu(&As[p][kk + t][m + 8]);
                af[mi][2] = ldu(&As[p][kk + t + 4][m]); af[mi][3] = ldu(&As[p][kk + t + 4][m + 8]);
            }
#pragma unroll
            for (int ni = 0; ni < 4; ++ni) {
                int n = nbase + ni * 8 + g;
                bf[ni][0] = ldu(&Bs[p][kk + t][n]); bf[ni][1] = ldu(&Bs[p][kk + t + 4][n]);
            }
#pragma unroll
            for (int mi = 0; mi < 4; ++mi)
#pragma unroll
                for (int ni = 0; ni < 4; ++ni)
                    mma8(acc[mi][ni], af[mi][0], af[mi][1], af[mi][2], af[mi][3],
                         bf[ni][0], bf[ni][1]);
        }
        __syncthreads();
    }
#pragma unroll
    for (int mi = 0; mi < 4; ++mi) {
        int qA = q0 + mbase + mi * 16 + g;
        float i0 = 1.0f / g_csum2[b * LQq + qA];
        float i1 = 1.0f / g_csum2[b * LQq + qA + 8];
        float* r0 = g_M + ((size_t)b * LQq + qA) * ND + d0;
        float* r1 = r0 + 8 * ND;
#pragma unroll
        for (int ni = 0; ni < 4; ++ni) {
            int d = nbase + ni * 8 + 2 * t;
            *(float2*)(r0 + d) = make_float2(f2tf(acc[mi][ni].x * i0), f2tf(acc[mi][ni].y * i0));
            *(float2*)(r1 + d) = make_float2(f2tf(acc[mi][ni].z * i1), f2tf(acc[mi][ni].w * i1));
        }
    }
}

// ---- k5: A = S1@Qtf, B_ = S1@M; cp.async; fused transposed-concat --------------
__global__ __launch_bounds__(256, 2) void k5_out(const float* __restrict__ C,
                                                 float* __restrict__ out) {
    __shared__ __align__(16) float smem[9728];
    float (*As)[128][20] = (float(*)[128][20])smem;          // 2*2560
    float (*Bq)[16][72]  = (float(*)[16][72])(smem + 5120);  // 2*1152
    float (*Bm)[16][72]  = (float(*)[16][72])(smem + 7424);  // 2*1152
    float (*Cs)[65]      = (float(*)[65])smem;               // epilogue
    float (*Tr)[69]      = (float(*)[69])(smem + 4160);      // epilogue
    const int b = blockIdx.z, c0 = blockIdx.y * 128, d0 = blockIdx.x * 64;
    const int tid = threadIdx.x, lane = tid & 31, w = tid >> 5;
    const int g = lane >> 2, t = lane & 3;
    const int wr = w >> 1, wc = w & 1;
    const int mbase = wr * 32, nbase = wc * 32;
    const int rowc = tid >> 1, hf = (tid & 1) * 8;
    const int qrr = tid >> 4, segq = (tid & 15) * 4;
    const float* Ag = g_E + ((size_t)b * LCc + c0 + rowc) * LQq + hf;
    const float* Qg = g_Qtf + (size_t)qrr * (NB * ND) + (size_t)b * ND + d0 + segq;
    const float* Mg = g_M + ((size_t)b * LQq + qrr) * ND + d0 + segq;
    const u32 Ad  = smem_u32(&As[0][rowc][hf]);
    const u32 Bqd = smem_u32(&Bq[0][qrr][segq]);
    const u32 Bmd = smem_u32(&Bm[0][qrr][segq]);
    cpa16(Ad, Ag); cpa16(Ad + 16, Ag + 4);
    cpa16(Bqd, Qg); cpa16(Bmd, Mg);
    cpa_commit();
    float4 accA[2][4] = {}, accB[2][4] = {};
    for (int ch = 0; ch < 32; ++ch) {
        const int p = ch & 1;
        if (ch < 31) {
            const int ko = (ch + 1) * 16;
            const u32 offA = (u32)((p ^ 1) * 10240);
            const u32 offB = (u32)((p ^ 1) * 4608);
            cpa16(Ad + offA, Ag + ko); cpa16(Ad + offA + 16, Ag + ko + 4);
            cpa16(Bqd + offB, Qg + (size_t)ko * (NB * ND));
            cpa16(Bmd + offB, Mg + (size_t)ko * ND);
            cpa_commit();
            cpa_wait<1>();
        } else cpa_wait<0>();
        __syncthreads();
#pragma unroll
        for (int kk = 0; kk < 16; kk += 8) {
            u32 af[2][4], qf[4][2], mf[4][2];
#pragma unroll
            for (int mi = 0; mi < 2; ++mi) {
                int m = mbase + mi * 16 + g;
                af[mi][0] = ldu(&As[p][m][kk + t]);
                af[mi][1] = ldu(&As[p][m + 8][kk + t]);
                af[mi][2] = ldu(&As[p][m][kk + t + 4]);
                af[mi][3] = ldu(&As[p][m + 8][kk + t + 4]);
            }
#pragma unroll
            for (int ni = 0; ni < 4; ++ni) {
                int n = nbase + ni * 8 + g;
                qf[ni][0] = ldu(&Bq[p][kk + t][n]); qf[ni][1] = ldu(&Bq[p][kk + t + 4][n]);
                mf[ni][0] = ldu(&Bm[p][kk + t][n]); mf[ni][1] = ldu(&Bm[p][kk + t + 4][n]);
            }
#pragma unroll
            for (int mi = 0; mi < 2; ++mi)
#pragma unroll
                for (int ni = 0; ni < 4; ++ni) {
                    mma8(accA[mi][ni], af[mi][0], af[mi][1], af[mi][2], af[mi][3],
                         qf[ni][0], qf[ni][1]);
                    mma8(accB[mi][ni], af[mi][0], af[mi][1], af[mi][2], af[mi][3],
                         mf[ni][0], mf[ni][1]);
                }
        }
        __syncthreads();
    }
#pragma unroll
    for (int mi = 0; mi < 2; ++mi) {
        int cA = c0 + mbase + mi * 16 + g;
        float i0 = g_invrs[b * LCc + cA];
        float i1 = g_invrs[b * LCc + cA + 8];
#pragma unroll
        for (int ni = 0; ni < 4; ++ni) {
            accA[mi][ni].x *= i0; accA[mi][ni].y *= i0;
            accA[mi][ni].z *= i1; accA[mi][ni].w *= i1;
            accB[mi][ni].x *= i0; accB[mi][ni].y *= i0;
            accB[mi][ni].z *= i1; accB[mi][ni].w *= i1;
        }
    }
    const int cl = tid & 63, dseg = (tid >> 6) * 16;
    const int cr = tid & 63, db = tid >> 6;
    const size_t ob = (size_t)b * (4 * ND) * LCc;
    for (int h = 0; h < 2; ++h) {
        __syncthreads();
        {
            const float* Cg = C + (size_t)(c0 + h * 64 + cl) * (NB * ND) + (size_t)b * ND + d0 + dseg;
#pragma unroll
            for (int dd = 0; dd < 16; dd += 4) {
                float4 cv = *(const float4*)(Cg + dd);
                Cs[dseg + dd + 0][cl] = cv.x; Cs[dseg + dd + 1][cl] = cv.y;
                Cs[dseg + dd + 2][cl] = cv.z; Cs[dseg + dd + 3][cl] = cv.w;
            }
        }
        if ((w >> 2) == h) {
#pragma unroll
            for (int mi = 0; mi < 2; ++mi) {
                int clh = (wr & 1) * 32 + mi * 16 + g;
#pragma unroll
                for (int ni = 0; ni < 4; ++ni) {
                    int d = nbase + ni * 8 + 2 * t;
                    Tr[clh][d] = accA[mi][ni].x;     Tr[clh][d + 1] = accA[mi][ni].y;
                    Tr[clh + 8][d] = accA[mi][ni].z; Tr[clh + 8][d + 1] = accA[mi][ni].w;
                }
            }
        }
        __syncthreads();
#pragma unroll
        for (int rr = 0; rr < 16; ++rr) {
            int dr = db + rr * 4;
            float cval = Cs[dr][cr];
            float aval = Tr[cr][dr];
            size_t col = (size_t)(c0 + h * 64 + cr);
            out[ob + (size_t)(d0 + dr) * LCc + col]          = cval;
            out[ob + (size_t)(ND + d0 + dr) * LCc + col]     = aval;
            out[ob + (size_t)(2 * ND + d0 + dr) * LCc + col] = cval * aval;
        }
        __syncthreads();
        if ((w >> 2) == h) {
#pragma unroll
            for (int mi = 0; mi < 2; ++mi) {
                int clh = (wr & 1) * 32 + mi * 16 + g;
#pragma unroll
                for (int ni = 0; ni < 4; ++ni) {
                    int d = nbase + ni * 8 + 2 * t;
                    Tr[clh][d] = accB[mi][ni].x;     Tr[clh][d + 1] = accB[mi][ni].y;
                    Tr[clh + 8][d] = accB[mi][ni].z; Tr[clh + 8][d + 1] = accB[mi][ni].w;
                }
            }
        }
        __syncthreads();
#pragma unroll
        for (int rr = 0; rr < 16; ++rr) {
            int dr = db + rr * 4;
            out[ob + (size_t)(3 * ND + d0 + dr) * LCc + (size_t)(c0 + h * 64 + cr)] =
                Cs[dr][cr] * Tr[cr][dr];
        }
    }
}

extern "C" void kernel_launch(void* const* d_in, const int* in_sizes, int n_in,
                              void* d_out, int out_size) {
    const float* C     = (const float*)d_in[0];
    const float* Q     = (const float*)d_in[1];
    const float* w4C   = (const float*)d_in[2];
    const float* w4Q   = (const float*)d_in[3];
    const float* w4mlu = (const float*)d_in[4];
    const float* bias  = (const float*)d_in[5];
    float* out = (float*)d_out;

    k_init<<<(NB * LCc + 255) / 256, 256>>>();
    k0_sub<<<(NB * LCc + NB * LQq) / 8, 256>>>(C, Q, w4C, w4Q);
    k0q<<<(LQq * NB * ND / 4 + 255) / 256, 256>>>(Q, w4mlu);
    k0c<<<(LCc * NB * ND / 4 + 255) / 256, 256>>>(C);
    k1_scores<<<dim3(LQq / 128, LCc / 128, NB), 256>>>(bias);
    k_fin<<<(NB * LCc + 255) / 256, 256>>>();
    k4_M<<<dim3(ND / 128, LQq / 128, NB), 256>>>();
    k5_out<<<dim3(ND / 64, LCc / 128, NB), 256>>>(C, out);
}

// round 11
// speedup vs baseline: 1.7071x; 1.1157x over previous
#include <cuda_runtime.h>
#include <cuda_fp16.h>
#include <math.h>

#define LCc 1024
#define LQq 512
#define NB  64
#define ND  256

typedef unsigned int u32;

__device__ float  g_E[(size_t)NB * LCc * LQq];    // tf32-rounded exp(S)
__device__ float  g_M[(size_t)NB * LQq * ND];     // tf32-rounded M
__device__ float  g_Ctf[(size_t)LCc * NB * ND];   // tf32-rounded C   (k4 B)
__device__ float  g_Qtf[(size_t)LQq * NB * ND];   // tf32-rounded Q   (k5 Bq)
__device__ __half g_Ch [(size_t)LCc * NB * ND];   // fp16 C           (k1 A)
__device__ __half g_Qwh[(size_t)LQq * NB * ND];   // fp16 Q*wml       (k1 B)
__device__ float g_sub0[NB * LCc];
__device__ float g_sub1[NB * LQq];
__device__ float g_rsum[NB * LCc];
__device__ float g_invrs[NB * LCc];
__device__ float g_csum2[NB * LQq];

// ---------------- helpers -----------------------------------------------------
__device__ __forceinline__ float f2tf(float f) {
    u32 r; asm("cvt.rna.tf32.f32 %0, %1;" : "=r"(r) : "f"(f));
    return __uint_as_float(r);
}
__device__ __forceinline__ void mma8(float4& d,
        u32 a0, u32 a1, u32 a2, u32 a3, u32 b0, u32 b1) {
    asm volatile("mma.sync.aligned.m16n8k8.row.col.f32.tf32.tf32.f32 "
        "{%0,%1,%2,%3}, {%4,%5,%6,%7}, {%8,%9}, {%0,%1,%2,%3};"
        : "+f"(d.x), "+f"(d.y), "+f"(d.z), "+f"(d.w)
        : "r"(a0), "r"(a1), "r"(a2), "r"(a3), "r"(b0), "r"(b1));
}
__device__ __forceinline__ void mma16(float4& d,
        u32 a0, u32 a1, u32 a2, u32 a3, u32 b0, u32 b1) {
    asm volatile("mma.sync.aligned.m16n8k16.row.col.f32.f16.f16.f32 "
        "{%0,%1,%2,%3}, {%4,%5,%6,%7}, {%8,%9}, {%0,%1,%2,%3};"
        : "+f"(d.x), "+f"(d.y), "+f"(d.z), "+f"(d.w)
        : "r"(a0), "r"(a1), "r"(a2), "r"(a3), "r"(b0), "r"(b1));
}
__device__ __forceinline__ u32 ldu(const float* p) { return __float_as_uint(*p); }
__device__ __forceinline__ u32 smem_u32(const void* p) {
    u32 a; asm("{ .reg .u64 t; cvta.to.shared.u64 t, %1; cvt.u32.u64 %0, t; }"
               : "=r"(a) : "l"(p));
    return a;
}
__device__ __forceinline__ void cpa16(u32 dst, const void* src) {
    asm volatile("cp.async.cg.shared.global [%0], [%1], 16;" :: "r"(dst), "l"(src) : "memory");
}
__device__ __forceinline__ void cpa_commit() {
    asm volatile("cp.async.commit_group;" ::: "memory");
}
template<int N>
__device__ __forceinline__ void cpa_wait() {
    asm volatile("cp.async.wait_group %0;" :: "n"(N) : "memory");
}
__device__ __forceinline__ __half h_rn(float f) { return __float2half_rn(f); }

// ---------------- small kernels ------------------------------------------------
__global__ void k_init() {
    int i = blockIdx.x * blockDim.x + threadIdx.x;
    if (i < NB * LQq) g_csum2[i] = 0.f;
    if (i < NB * LCc) g_rsum[i] = 0.f;
}
__global__ void k_fin() {
    int i = blockIdx.x * blockDim.x + threadIdx.x;
    if (i < NB * LCc) g_invrs[i] = 1.0f / g_rsum[i];
}

__global__ __launch_bounds__(256) void k0_sub(const float* __restrict__ C,
                                              const float* __restrict__ Q,
                                              const float* __restrict__ w4C,
                                              const float* __restrict__ w4Q) {
    int gw   = (blockIdx.x * blockDim.x + threadIdx.x) >> 5;
    int lane = threadIdx.x & 31;
    const float* src; const float* w; float* dst;
    if (gw < NB * LCc) {
        src = C + (size_t)gw * ND; w = w4C;
        int c = gw / NB, b = gw % NB;
        dst = g_sub0 + b * LCc + c;
    } else {
        int r = gw - NB * LCc;
        if (r >= NB * LQq) return;
        src = Q + (size_t)r * ND; w = w4Q;
        int q = r / NB, b = r % NB;
        dst = g_sub1 + b * LQq + q;
    }
    float acc = 0.f;
    const float4* s4 = (const float4*)src;
    const float4* w4 = (const float4*)w;
#pragma unroll
    for (int j = 0; j < 2; ++j) {
        float4 a = s4[lane + 32 * j], ww = w4[lane + 32 * j];
        acc += a.x * ww.x + a.y * ww.y + a.z * ww.z + a.w * ww.w;
    }
#pragma unroll
    for (int off = 16; off; off >>= 1) acc += __shfl_xor_sync(0xffffffffu, acc, off);
    if (lane == 0) *dst = acc;
}

// Q -> g_Qtf (tf32 f32) and g_Qwh (fp16 Q*wml)
__global__ __launch_bounds__(256) void k0q(const float* __restrict__ Q,
                                           const float* __restrict__ wml) {
    int i = blockIdx.x * blockDim.x + threadIdx.x;
    if (i >= LQq * NB * ND / 4) return;
    float4 v = ((const float4*)Q)[i];
    float4 ww = ((const float4*)wml)[i & 63];
    ((float4*)g_Qtf)[i] = make_float4(f2tf(v.x), f2tf(v.y), f2tf(v.z), f2tf(v.w));
    __half2* qw = (__half2*)(g_Qwh + (size_t)i * 4);
    qw[0] = __halves2half2(h_rn(v.x * ww.x), h_rn(v.y * ww.y));
    qw[1] = __halves2half2(h_rn(v.z * ww.z), h_rn(v.w * ww.w));
}
// C -> g_Ctf (tf32 f32) and g_Ch (fp16)
__global__ __launch_bounds__(256) void k0c(const float* __restrict__ C) {
    int i = blockIdx.x * blockDim.x + threadIdx.x;
    if (i >= LCc * NB * ND / 4) return;
    float4 v = ((const float4*)C)[i];
    ((float4*)g_Ctf)[i] = make_float4(f2tf(v.x), f2tf(v.y), f2tf(v.z), f2tf(v.w));
    __half2* ch = (__half2*)(g_Ch + (size_t)i * 4);
    ch[0] = __halves2half2(h_rn(v.x), h_rn(v.y));
    ch[1] = __halves2half2(h_rn(v.z), h_rn(v.w));
}

// ---- k1 (fp16 HMMA): E = tf32(exp(Ch @ Qwh^T + sub0 + sub1 + bias)); fused sums
// CTA 128(c) x 128(q), K=d 256 in 8 chunks of 32; smem [m][k] halves pad 40
__global__ __launch_bounds__(256, 2) void k1_scores(const float* __restrict__ bias) {
    __shared__ __half As[2][128][40];
    __shared__ __half Bs[2][128][40];
    const int tid = threadIdx.x, lane = tid & 31, w = tid >> 5;
    const int g = lane >> 2, t = lane & 3;
    const int b = blockIdx.z, c0 = blockIdx.y * 128, q0 = blockIdx.x * 128;
    const int mbase = (w >> 2) * 64, nbase = (w & 3) * 32;
    const int row = tid >> 1, sg = (tid & 1) * 16;
    const __half* Ag = g_Ch + ((size_t)(c0 + row) * NB + b) * ND + sg;
    const __half* Bg = g_Qwh + ((size_t)(q0 + row) * NB + b) * ND + sg;
    const u32 Ad = smem_u32(&As[0][row][sg]);
    const u32 Bd = smem_u32(&Bs[0][row][sg]);
    cpa16(Ad, Ag); cpa16(Ad + 16, Ag + 8);
    cpa16(Bd, Bg); cpa16(Bd + 16, Bg + 8);
    cpa_commit();
    float4 acc[4][4] = {};
    for (int ch = 0; ch < 8; ++ch) {
        const int p = ch & 1;
        if (ch < 7) {
            const int ko = (ch + 1) * 32;
            const u32 off = (u32)((p ^ 1) * 10240);
            cpa16(Ad + off, Ag + ko); cpa16(Ad + off + 16, Ag + ko + 8);
            cpa16(Bd + off, Bg + ko); cpa16(Bd + off + 16, Bg + ko + 8);
            cpa_commit();
            cpa_wait<1>();
        } else cpa_wait<0>();
        __syncthreads();
#pragma unroll
        for (int kk = 0; kk < 32; kk += 16) {
            u32 af[4][4], bf[4][2];
#pragma unroll
            for (int mi = 0; mi < 4; ++mi) {
                int m = mbase + mi * 16 + g;
                af[mi][0] = *(const u32*)&As[p][m][kk + 2 * t];
                af[mi][1] = *(const u32*)&As[p][m + 8][kk + 2 * t];
                af[mi][2] = *(const u32*)&As[p][m][kk + 2 * t + 8];
                af[mi][3] = *(const u32*)&As[p][m + 8][kk + 2 * t + 8];
            }
#pragma unroll
            for (int ni = 0; ni < 4; ++ni) {
                int n = nbase + ni * 8 + g;
                bf[ni][0] = *(const u32*)&Bs[p][n][kk + 2 * t];
                bf[ni][1] = *(const u32*)&Bs[p][n][kk + 2 * t + 8];
            }
#pragma unroll
            for (int mi = 0; mi < 4; ++mi)
#pragma unroll
                for (int ni = 0; ni < 4; ++ni)
                    mma16(acc[mi][ni], af[mi][0], af[mi][1], af[mi][2], af[mi][3],
                          bf[ni][0], bf[ni][1]);
        }
        __syncthreads();
    }
    const float bv = bias[0];
    float s1x[4], s1y[4];
#pragma unroll
    for (int ni = 0; ni < 4; ++ni) {
        int q = q0 + nbase + ni * 8 + 2 * t;
        s1x[ni] = g_sub1[b * LQq + q];
        s1y[ni] = g_sub1[b * LQq + q + 1];
    }
    float rs0[4] = {}, rs1[4] = {}, ccx[4] = {}, ccy[4] = {};
#pragma unroll
    for (int mi = 0; mi < 4; ++mi) {
        int cA = c0 + mbase + mi * 16 + g;
        float s0a = g_sub0[b * LCc + cA] + bv;
        float s0b = g_sub0[b * LCc + cA + 8] + bv;
        float* r0 = g_E + ((size_t)b * LCc + cA) * LQq + q0;
        float* r1 = r0 + (size_t)8 * LQq;
#pragma unroll
        for (int ni = 0; ni < 4; ++ni) {
            int q = nbase + ni * 8 + 2 * t;
            float2 e0 = {f2tf(expf(acc[mi][ni].x + s0a + s1x[ni])),
                         f2tf(expf(acc[mi][ni].y + s0a + s1y[ni]))};
            float2 e1 = {f2tf(expf(acc[mi][ni].z + s0b + s1x[ni])),
                         f2tf(expf(acc[mi][ni].w + s0b + s1y[ni]))};
            *(float2*)(r0 + q) = e0;
            *(float2*)(r1 + q) = e1;
            rs0[mi] += e0.x + e0.y; rs1[mi] += e1.x + e1.y;
            ccx[ni] += e0.x + e1.x; ccy[ni] += e0.y + e1.y;
        }
    }
#pragma unroll
    for (int mi = 0; mi < 4; ++mi) {
        float a = rs0[mi], c2 = rs1[mi];
        a  += __shfl_xor_sync(0xffffffffu, a, 1);  a  += __shfl_xor_sync(0xffffffffu, a, 2);
        c2 += __shfl_xor_sync(0xffffffffu, c2, 1); c2 += __shfl_xor_sync(0xffffffffu, c2, 2);
        if (t == 0) {
            int cA = c0 + mbase + mi * 16 + g;
            atomicAdd(&g_rsum[b * LCc + cA], a);
            atomicAdd(&g_rsum[b * LCc + cA + 8], c2);
        }
    }
#pragma unroll
    for (int ni = 0; ni < 4; ++ni) {
        float x = ccx[ni], y = ccy[ni];
        x += __shfl_xor_sync(0xffffffffu, x, 4);  y += __shfl_xor_sync(0xffffffffu, y, 4);
        x += __shfl_xor_sync(0xffffffffu, x, 8);  y += __shfl_xor_sync(0xffffffffu, y, 8);
        x += __shfl_xor_sync(0xffffffffu, x, 16); y += __shfl_xor_sync(0xffffffffu, y, 16);
        if (g == 0) {
            int q = q0 + nbase + ni * 8 + 2 * t;
            atomicAdd(&g_csum2[b * LQq + q], x);
            atomicAdd(&g_csum2[b * LQq + q + 1], y);
        }
    }
}

// ---- k4: M = rna(E^T @ Ctf / colsum); tf32 path, verbatim R9 -------------------
__global__ __launch_bounds__(256, 2) void k4_M() {
    __shared__ float As[2][16][136];
    __shared__ float Bs[2][16][136];
    const int b = blockIdx.z, q0 = blockIdx.y * 128, d0 = blockIdx.x * 128;
    const int tid = threadIdx.x, lane = tid & 31, w = tid >> 5;
    const int g = lane >> 2, t = lane & 3;
    const int mbase = (w >> 2) * 64, nbase = (w & 3) * 32;
    const int crr = tid >> 4, seg = (tid & 15) * 8;
    const float* Ag = g_E + ((size_t)b * LCc + crr) * LQq + q0 + seg;
    const float* Bg = g_Ctf + (size_t)crr * (NB * ND) + (size_t)b * ND + d0 + seg;
    const u32 Ad = smem_u32(&As[0][crr][seg]);
    const u32 Bd = smem_u32(&Bs[0][crr][seg]);
    cpa16(Ad, Ag); cpa16(Ad + 16, Ag + 4);
    cpa16(Bd, Bg); cpa16(Bd + 16, Bg + 4);
    cpa_commit();
    float4 acc[4][4] = {};
    for (int ch = 0; ch < 64; ++ch) {
        const int p = ch & 1;
        if (ch < 63) {
            const size_t ca = (size_t)(ch + 1) * 16;
            const u32 off = (u32)((p ^ 1) * 8704);
            cpa16(Ad + off, Ag + ca * LQq); cpa16(Ad + off + 16, Ag + ca * LQq + 4);
            cpa16(Bd + off, Bg + ca * (NB * ND)); cpa16(Bd + off + 16, Bg + ca * (NB * ND) + 4);
            cpa_commit();
            cpa_wait<1>();
        } else cpa_wait<0>();
        __syncthreads();
#pragma unroll
        for (int kk = 0; kk < 16; kk += 8) {
            u32 af[4][4], bf[4][2];
#pragma unroll
            for (int mi = 0; mi < 4; ++mi) {
                int m = mbase + mi * 16 + g;
                af[mi][0] = ldu(&As[p][kk + t][m]);     af[mi][1] = ldu(&As[p][kk + t][m + 8]);
                af[mi][2] = ldu(&As[p][kk + t + 4][m]); af[mi][3] = ldu(&As[p][kk + t + 4][m + 8]);
            }
#pragma unroll
            for (int ni = 0; ni < 4; ++ni) {
                int n = nbase + ni * 8 + g;
                bf[ni][0] = ldu(&Bs[p][kk + t][n]); bf[ni][1] = ldu(&Bs[p][kk + t + 4][n]);
            }
#pragma unroll
            for (int mi = 0; mi < 4; ++mi)
#pragma unroll
                for (int ni = 0; ni < 4; ++ni)
                    mma8(acc[mi][ni], af[mi][0], af[mi][1], af[mi][2], af[mi][3],
                         bf[ni][0], bf[ni][1]);
        }
        __syncthreads();
    }
#pragma unroll
    for (int mi = 0; mi < 4; ++mi) {
        int qA = q0 + mbase + mi * 16 + g;
        float i0 = 1.0f / g_csum2[b * LQq + qA];
        float i1 = 1.0f / g_csum2[b * LQq + qA + 8];
        float* r0 = g_M + ((size_t)b * LQq + qA) * ND + d0;
        float* r1 = r0 + 8 * ND;
#pragma unroll
        for (int ni = 0; ni < 4; ++ni) {
            int d = nbase + ni * 8 + 2 * t;
            *(float2*)(r0 + d) = make_float2(f2tf(acc[mi][ni].x * i0), f2tf(acc[mi][ni].y * i0));
            *(float2*)(r1 + d) = make_float2(f2tf(acc[mi][ni].z * i1), f2tf(acc[mi][ni].w * i1));
        }
    }
}

// ---- k5: A = S1@Qtf, B_ = S1@M; tf32 path, verbatim R9 -------------------------
__global__ __launch_bounds__(256, 2) void k5_out(const float* __restrict__ C,
                                                 float* __restrict__ out) {
    __shared__ __align__(16) float smem[9728];
    float (*As)[128][20] = (float(*)[128][20])smem;          // 2*2560
    float (*Bq)[16][72]  = (float(*)[16][72])(smem + 5120);  // 2*1152
    float (*Bm)[16][72]  = (float(*)[16][72])(smem + 7424);  // 2*1152
    float (*Cs)[65]      = (float(*)[65])smem;               // epilogue
    float (*Tr)[69]      = (float(*)[69])(smem + 4160);      // epilogue
    const int b = blockIdx.z, c0 = blockIdx.y * 128, d0 = blockIdx.x * 64;
    const int tid = threadIdx.x, lane = tid & 31, w = tid >> 5;
    const int g = lane >> 2, t = lane & 3;
    const int wr = w >> 1, wc = w & 1;
    const int mbase = wr * 32, nbase = wc * 32;
    const int rowc = tid >> 1, hf = (tid & 1) * 8;
    const int qrr = tid >> 4, segq = (tid & 15) * 4;
    const float* Ag = g_E + ((size_t)b * LCc + c0 + rowc) * LQq + hf;
    const float* Qg = g_Qtf + (size_t)qrr * (NB * ND) + (size_t)b * ND + d0 + segq;
    const float* Mg = g_M + ((size_t)b * LQq + qrr) * ND + d0 + segq;
    const u32 Ad  = smem_u32(&As[0][rowc][hf]);
    const u32 Bqd = smem_u32(&Bq[0][qrr][segq]);
    const u32 Bmd = smem_u32(&Bm[0][qrr][segq]);
    cpa16(Ad, Ag); cpa16(Ad + 16, Ag + 4);
    cpa16(Bqd, Qg); cpa16(Bmd, Mg);
    cpa_commit();
    float4 accA[2][4] = {}, accB[2][4] = {};
    for (int ch = 0; ch < 32; ++ch) {
        const int p = ch & 1;
        if (ch < 31) {
            const int ko = (ch + 1) * 16;
            const u32 offA = (u32)((p ^ 1) * 10240);
            const u32 offB = (u32)((p ^ 1) * 4608);
            cpa16(Ad + offA, Ag + ko); cpa16(Ad + offA + 16, Ag + ko + 4);
            cpa16(Bqd + offB, Qg + (size_t)ko * (NB * ND));
            cpa16(Bmd + offB, Mg + (size_t)ko * ND);
            cpa_commit();
            cpa_wait<1>();
        } else cpa_wait<0>();
        __syncthreads();
#pragma unroll
        for (int kk = 0; kk < 16; kk += 8) {
            u32 af[2][4], qf[4][2], mf[4][2];
#pragma unroll
            for (int mi = 0; mi < 2; ++mi) {
                int m = mbase + mi * 16 + g;
                af[mi][0] = ldu(&As[p][m][kk + t]);
                af[mi][1] = ldu(&As[p][m + 8][kk + t]);
                af[mi][2] = ldu(&As[p][m][kk + t + 4]);
                af[mi][3] = ldu(&As[p][m + 8][kk + t + 4]);
            }
#pragma unroll
            for (int ni = 0; ni < 4; ++ni) {
                int n = nbase + ni * 8 + g;
                qf[ni][0] = ldu(&Bq[p][kk + t][n]); qf[ni][1] = ldu(&Bq[p][kk + t + 4][n]);
                mf[ni][0] = ldu(&Bm[p][kk + t][n]); mf[ni][1] = ldu(&Bm[p][kk + t + 4][n]);
            }
#pragma unroll
            for (int mi = 0; mi < 2; ++mi)
#pragma unroll
                for (int ni = 0; ni < 4; ++ni) {
                    mma8(accA[mi][ni], af[mi][0], af[mi][1], af[mi][2], af[mi][3],
                         qf[ni][0], qf[ni][1]);
                    mma8(accB[mi][ni], af[mi][0], af[mi][1], af[mi][2], af[mi][3],
                         mf[ni][0], mf[ni][1]);
                }
        }
        __syncthreads();
    }
#pragma unroll
    for (int mi = 0; mi < 2; ++mi) {
        int cA = c0 + mbase + mi * 16 + g;
        float i0 = g_invrs[b * LCc + cA];
        float i1 = g_invrs[b * LCc + cA + 8];
#pragma unroll
        for (int ni = 0; ni < 4; ++ni) {
            accA[mi][ni].x *= i0; accA[mi][ni].y *= i0;
            accA[mi][ni].z *= i1; accA[mi][ni].w *= i1;
            accB[mi][ni].x *= i0; accB[mi][ni].y *= i0;
            accB[mi][ni].z *= i1; accB[mi][ni].w *= i1;
        }
    }
    const int cl = tid & 63, dseg = (tid >> 6) * 16;
    const int cr = tid & 63, db = tid >> 6;
    const size_t ob = (size_t)b * (4 * ND) * LCc;
    for (int h = 0; h < 2; ++h) {
        __syncthreads();
        {
            const float* Cg = C + (size_t)(c0 + h * 64 + cl) * (NB * ND) + (size_t)b * ND + d0 + dseg;
#pragma unroll
            for (int dd = 0; dd < 16; dd += 4) {
                float4 cv = *(const float4*)(Cg + dd);
                Cs[dseg + dd + 0][cl] = cv.x; Cs[dseg + dd + 1][cl] = cv.y;
                Cs[dseg + dd + 2][cl] = cv.z; Cs[dseg + dd + 3][cl] = cv.w;
            }
        }
        if ((w >> 2) == h) {
#pragma unroll
            for (int mi = 0; mi < 2; ++mi) {
                int clh = (wr & 1) * 32 + mi * 16 + g;
#pragma unroll
                for (int ni = 0; ni < 4; ++ni) {
                    int d = nbase + ni * 8 + 2 * t;
                    Tr[clh][d] = accA[mi][ni].x;     Tr[clh][d + 1] = accA[mi][ni].y;
                    Tr[clh + 8][d] = accA[mi][ni].z; Tr[clh + 8][d + 1] = accA[mi][ni].w;
                }
            }
        }
        __syncthreads();
#pragma unroll
        for (int rr = 0; rr < 16; ++rr) {
            int dr = db + rr * 4;
            float cval = Cs[dr][cr];
            float aval = Tr[cr][dr];
            size_t col = (size_t)(c0 + h * 64 + cr);
            out[ob + (size_t)(d0 + dr) * LCc + col]          = cval;
            out[ob + (size_t)(ND + d0 + dr) * LCc + col]     = aval;
            out[ob + (size_t)(2 * ND + d0 + dr) * LCc + col] = cval * aval;
        }
        __syncthreads();
        if ((w >> 2) == h) {
#pragma unroll
            for (int mi = 0; mi < 2; ++mi) {
                int clh = (wr & 1) * 32 + mi * 16 + g;
#pragma unroll
                for (int ni = 0; ni < 4; ++ni) {
                    int d = nbase + ni * 8 + 2 * t;
                    Tr[clh][d] = accB[mi][ni].x;     Tr[clh][d + 1] = accB[mi][ni].y;
                    Tr[clh + 8][d] = accB[mi][ni].z; Tr[clh + 8][d + 1] = accB[mi][ni].w;
                }
            }
        }
        __syncthreads();
#pragma unroll
        for (int rr = 0; rr < 16; ++rr) {
            int dr = db + rr * 4;
            out[ob + (size_t)(3 * ND + d0 + dr) * LCc + (size_t)(c0 + h * 64 + cr)] =
                Cs[dr][cr] * Tr[cr][dr];
        }
    }
}

extern "C" void kernel_launch(void* const* d_in, const int* in_sizes, int n_in,
                              void* d_out, int out_size) {
    const float* C     = (const float*)d_in[0];
    const float* Q     = (const float*)d_in[1];
    const float* w4C   = (const float*)d_in[2];
    const float* w4Q   = (const float*)d_in[3];
    const float* w4mlu = (const float*)d_in[4];
    const float* bias  = (const float*)d_in[5];
    float* out = (float*)d_out;

    k_init<<<(NB * LCc + 255) / 256, 256>>>();
    k0_sub<<<(NB * LCc + NB * LQq) / 8, 256>>>(C, Q, w4C, w4Q);
    k0q<<<(LQq * NB * ND / 4 + 255) / 256, 256>>>(Q, w4mlu);
    k0c<<<(LCc * NB * ND / 4 + 255) / 256, 256>>>(C);
    k1_scores<<<dim3(LQq / 128, LCc / 128, NB), 256>>>(bias);
    k_fin<<<(NB * LCc + 255) / 256, 256>>>();
    k4_M<<<dim3(ND / 128, LQq / 128, NB), 256>>>();
    k5_out<<<dim3(ND / 64, LCc / 128, NB), 256>>>(C, out);
}

// round 12
// speedup vs baseline: 2.1727x; 1.2728x over previous
#include <cuda_runtime.h>
#include <cuda_fp16.h>
#include <math.h>

#define LCc 1024
#define LQq 512
#define NB  64
#define ND  256

typedef unsigned int u32;

// fp16 operand arrays (pair-interleaved copies for k-major consumers)
__device__ __half g_Ch [(size_t)LCc * NB * ND];   // [c][b][d]            (k1 A)
__device__ __half g_C2 [(size_t)LCc * NB * ND];   // [c/2][b][d][c&1]     (k4 B)
__device__ __half g_Qwh[(size_t)LQq * NB * ND];   // [q][b][d]  Q*wml     (k1 B)
__device__ __half g_Q2 [(size_t)LQq * NB * ND];   // [q/2][b][d][q&1]     (k5 Bq)
__device__ __half g_Eh [(size_t)NB * LCc * LQq];  // [b][c][q]            (k5 A)
__device__ __half g_E2 [(size_t)NB * LCc * LQq];  // [b][c/2][q][c&1]     (k4 A)
__device__ __half g_M2 [(size_t)NB * LQq * ND];   // [b][q/2][d][q&1]     (k5 Bm)
__device__ float g_sub0[NB * LCc];
__device__ float g_sub1[NB * LQq];
__device__ float g_rsum[NB * LCc];
__device__ float g_invrs[NB * LCc];
__device__ float g_csum2[NB * LQq];

// ---------------- helpers -----------------------------------------------------
__device__ __forceinline__ void mma16(float4& d,
        u32 a0, u32 a1, u32 a2, u32 a3, u32 b0, u32 b1) {
    asm volatile("mma.sync.aligned.m16n8k16.row.col.f32.f16.f16.f32 "
        "{%0,%1,%2,%3}, {%4,%5,%6,%7}, {%8,%9}, {%0,%1,%2,%3};"
        : "+f"(d.x), "+f"(d.y), "+f"(d.z), "+f"(d.w)
        : "r"(a0), "r"(a1), "r"(a2), "r"(a3), "r"(b0), "r"(b1));
}
__device__ __forceinline__ u32 smem_u32(const void* p) {
    u32 a; asm("{ .reg .u64 t; cvta.to.shared.u64 t, %1; cvt.u32.u64 %0, t; }"
               : "=r"(a) : "l"(p));
    return a;
}
__device__ __forceinline__ void cpa16(u32 dst, const void* src) {
    asm volatile("cp.async.cg.shared.global [%0], [%1], 16;" :: "r"(dst), "l"(src) : "memory");
}
__device__ __forceinline__ void cpa_commit() {
    asm volatile("cp.async.commit_group;" ::: "memory");
}
template<int N>
__device__ __forceinline__ void cpa_wait() {
    asm volatile("cp.async.wait_group %0;" :: "n"(N) : "memory");
}
__device__ __forceinline__ __half h_rn(float f) { return __float2half_rn(f); }

// ---------------- small kernels ------------------------------------------------
__global__ void k_init() {
    int i = blockIdx.x * blockDim.x + threadIdx.x;
    if (i < NB * LQq) g_csum2[i] = 0.f;
    if (i < NB * LCc) g_rsum[i] = 0.f;
}
__global__ void k_fin() {
    int i = blockIdx.x * blockDim.x + threadIdx.x;
    if (i < NB * LCc) g_invrs[i] = 1.0f / g_rsum[i];
}

__global__ __launch_bounds__(256) void k0_sub(const float* __restrict__ C,
                                              const float* __restrict__ Q,
                                              const float* __restrict__ w4C,
                                              const float* __restrict__ w4Q) {
    int gw   = (blockIdx.x * blockDim.x + threadIdx.x) >> 5;
    int lane = threadIdx.x & 31;
    const float* src; const float* w; float* dst;
    if (gw < NB * LCc) {
        src = C + (size_t)gw * ND; w = w4C;
        int c = gw / NB, b = gw % NB;
        dst = g_sub0 + b * LCc + c;
    } else {
        int r = gw - NB * LCc;
        if (r >= NB * LQq) return;
        src = Q + (size_t)r * ND; w = w4Q;
        int q = r / NB, b = r % NB;
        dst = g_sub1 + b * LQq + q;
    }
    float acc = 0.f;
    const float4* s4 = (const float4*)src;
    const float4* w4 = (const float4*)w;
#pragma unroll
    for (int j = 0; j < 2; ++j) {
        float4 a = s4[lane + 32 * j], ww = w4[lane + 32 * j];
        acc += a.x * ww.x + a.y * ww.y + a.z * ww.z + a.w * ww.w;
    }
#pragma unroll
    for (int off = 16; off; off >>= 1) acc += __shfl_xor_sync(0xffffffffu, acc, off);
    if (lane == 0) *dst = acc;
}

// Q -> g_Qwh (Q*wml, [q][b][d]) and g_Q2 (raw Q, q-pair interleaved)
__global__ __launch_bounds__(256) void k0q(const float* __restrict__ Q,
                                           const float* __restrict__ wml) {
    int i = blockIdx.x * blockDim.x + threadIdx.x;
    if (i >= LQq * NB * ND / 4) return;
    float4 v = ((const float4*)Q)[i];
    float4 ww = ((const float4*)wml)[i & 63];
    int e = i * 4;
    int d = e & (ND - 1);
    int rqb = e >> 8;             // (q*NB + b)
    int b = rqb & (NB - 1);
    int q = rqb >> 6;
    __half2* qw = (__half2*)(g_Qwh + e);
    qw[0] = __halves2half2(h_rn(v.x * ww.x), h_rn(v.y * ww.y));
    qw[1] = __halves2half2(h_rn(v.z * ww.z), h_rn(v.w * ww.w));
    size_t p2 = ((size_t)((q >> 1) * NB + b) * ND + d) * 2 + (q & 1);
    g_Q2[p2]     = h_rn(v.x);
    g_Q2[p2 + 2] = h_rn(v.y);
    g_Q2[p2 + 4] = h_rn(v.z);
    g_Q2[p2 + 6] = h_rn(v.w);
}
// C -> g_Ch ([c][b][d]) and g_C2 (c-pair interleaved)
__global__ __launch_bounds__(256) void k0c(const float* __restrict__ C) {
    int i = blockIdx.x * blockDim.x + threadIdx.x;
    if (i >= LCc * NB * ND / 4) return;
    float4 v = ((const float4*)C)[i];
    int e = i * 4;
    int d = e & (ND - 1);
    int rcb = e >> 8;
    int b = rcb & (NB - 1);
    int c = rcb >> 6;
    __half2* ch = (__half2*)(g_Ch + e);
    ch[0] = __halves2half2(h_rn(v.x), h_rn(v.y));
    ch[1] = __halves2half2(h_rn(v.z), h_rn(v.w));
    size_t p2 = ((size_t)((c >> 1) * NB + b) * ND + d) * 2 + (c & 1);
    g_C2[p2]     = h_rn(v.x);
    g_C2[p2 + 2] = h_rn(v.y);
    g_C2[p2 + 4] = h_rn(v.z);
    g_C2[p2 + 6] = h_rn(v.w);
}

// ---- k1: E = exp(Ch @ Qwh^T + sub0 + sub1 + bias) -> g_Eh + g_E2; fused sums --
__global__ __launch_bounds__(256, 2) void k1_scores(const float* __restrict__ bias) {
    __shared__ __half As[2][128][40];
    __shared__ __half Bs[2][128][40];
    const int tid = threadIdx.x, lane = tid & 31, w = tid >> 5;
    const int g = lane >> 2, t = lane & 3;
    const int b = blockIdx.z, c0 = blockIdx.y * 128, q0 = blockIdx.x * 128;
    const int mbase = (w >> 2) * 64, nbase = (w & 3) * 32;
    const int row = tid >> 1, sg = (tid & 1) * 16;
    const __half* Ag = g_Ch + ((size_t)(c0 + row) * NB + b) * ND + sg;
    const __half* Bg = g_Qwh + ((size_t)(q0 + row) * NB + b) * ND + sg;
    const u32 Ad = smem_u32(&As[0][row][sg]);
    const u32 Bd = smem_u32(&Bs[0][row][sg]);
    cpa16(Ad, Ag); cpa16(Ad + 16, Ag + 8);
    cpa16(Bd, Bg); cpa16(Bd + 16, Bg + 8);
    cpa_commit();
    float4 acc[4][4] = {};
    for (int ch = 0; ch < 8; ++ch) {
        const int p = ch & 1;
        if (ch < 7) {
            const int ko = (ch + 1) * 32;
            const u32 off = (u32)((p ^ 1) * 10240);
            cpa16(Ad + off, Ag + ko); cpa16(Ad + off + 16, Ag + ko + 8);
            cpa16(Bd + off, Bg + ko); cpa16(Bd + off + 16, Bg + ko + 8);
            cpa_commit();
            cpa_wait<1>();
        } else cpa_wait<0>();
        __syncthreads();
#pragma unroll
        for (int kk = 0; kk < 32; kk += 16) {
            u32 af[4][4], bf[4][2];
#pragma unroll
            for (int mi = 0; mi < 4; ++mi) {
                int m = mbase + mi * 16 + g;
                af[mi][0] = *(const u32*)&As[p][m][kk + 2 * t];
                af[mi][1] = *(const u32*)&As[p][m + 8][kk + 2 * t];
                af[mi][2] = *(const u32*)&As[p][m][kk + 2 * t + 8];
                af[mi][3] = *(const u32*)&As[p][m + 8][kk + 2 * t + 8];
            }
#pragma unroll
            for (int ni = 0; ni < 4; ++ni) {
                int n = nbase + ni * 8 + g;
                bf[ni][0] = *(const u32*)&Bs[p][n][kk + 2 * t];
                bf[ni][1] = *(const u32*)&Bs[p][n][kk + 2 * t + 8];
            }
#pragma unroll
            for (int mi = 0; mi < 4; ++mi)
#pragma unroll
                for (int ni = 0; ni < 4; ++ni)
                    mma16(acc[mi][ni], af[mi][0], af[mi][1], af[mi][2], af[mi][3],
                          bf[ni][0], bf[ni][1]);
        }
        __syncthreads();
    }
    const float bv = bias[0];
    float s1x[4], s1y[4];
#pragma unroll
    for (int ni = 0; ni < 4; ++ni) {
        int q = q0 + nbase + ni * 8 + 2 * t;
        s1x[ni] = g_sub1[b * LQq + q];
        s1y[ni] = g_sub1[b * LQq + q + 1];
    }
    float rs0[4] = {}, rs1[4] = {}, ccx[4] = {}, ccy[4] = {};
#pragma unroll
    for (int mi = 0; mi < 4; ++mi) {
        int cA = c0 + mbase + mi * 16 + g;
        float s0a = g_sub0[b * LCc + cA] + bv;
        float s0b = g_sub0[b * LCc + cA + 8] + bv;
        __half* r0 = g_Eh + (size_t)(b * LCc + cA) * LQq + q0;
        __half* r1 = r0 + (size_t)8 * LQq;
        size_t e20 = ((size_t)(b * (LCc / 2) + (cA >> 1)) * LQq + q0) * 2 + (cA & 1);
        size_t e21 = e20 + (size_t)8 * LQq;
#pragma unroll
        for (int ni = 0; ni < 4; ++ni) {
            int q = nbase + ni * 8 + 2 * t;
            __half h00 = h_rn(expf(acc[mi][ni].x + s0a + s1x[ni]));
            __half h01 = h_rn(expf(acc[mi][ni].y + s0a + s1y[ni]));
            __half h10 = h_rn(expf(acc[mi][ni].z + s0b + s1x[ni]));
            __half h11 = h_rn(expf(acc[mi][ni].w + s0b + s1y[ni]));
            *(__half2*)(r0 + q) = __halves2half2(h00, h01);
            *(__half2*)(r1 + q) = __halves2half2(h10, h11);
            g_E2[e20 + 2 * q] = h00; g_E2[e20 + 2 * q + 2] = h01;
            g_E2[e21 + 2 * q] = h10; g_E2[e21 + 2 * q + 2] = h11;
            float f00 = __half2float(h00), f01 = __half2float(h01);
            float f10 = __half2float(h10), f11 = __half2float(h11);
            rs0[mi] += f00 + f01; rs1[mi] += f10 + f11;
            ccx[ni] += f00 + f10; ccy[ni] += f01 + f11;
        }
    }
#pragma unroll
    for (int mi = 0; mi < 4; ++mi) {
        float a = rs0[mi], c2 = rs1[mi];
        a  += __shfl_xor_sync(0xffffffffu, a, 1);  a  += __shfl_xor_sync(0xffffffffu, a, 2);
        c2 += __shfl_xor_sync(0xffffffffu, c2, 1); c2 += __shfl_xor_sync(0xffffffffu, c2, 2);
        if (t == 0) {
            int cA = c0 + mbase + mi * 16 + g;
            atomicAdd(&g_rsum[b * LCc + cA], a);
            atomicAdd(&g_rsum[b * LCc + cA + 8], c2);
        }
    }
#pragma unroll
    for (int ni = 0; ni < 4; ++ni) {
        float x = ccx[ni], y = ccy[ni];
        x += __shfl_xor_sync(0xffffffffu, x, 4);  y += __shfl_xor_sync(0xffffffffu, y, 4);
        x += __shfl_xor_sync(0xffffffffu, x, 8);  y += __shfl_xor_sync(0xffffffffu, y, 8);
        x += __shfl_xor_sync(0xffffffffu, x, 16); y += __shfl_xor_sync(0xffffffffu, y, 16);
        if (g == 0) {
            int q = q0 + nbase + ni * 8 + 2 * t;
            atomicAdd(&g_csum2[b * LQq + q], x);
            atomicAdd(&g_csum2[b * LQq + q + 1], y);
        }
    }
}

// ---- k4: M2 = (E^T @ C / colsum); A=g_E2, B=g_C2 -------------------------------
__global__ __launch_bounds__(256, 2) void k4_M() {
    __shared__ __half As[2][16][272];
    __shared__ __half Bs[2][16][272];
    const int b = blockIdx.z, q0 = blockIdx.y * 128, d0 = blockIdx.x * 128;
    const int tid = threadIdx.x, lane = tid & 31, w = tid >> 5;
    const int g = lane >> 2, t = lane & 3;
    const int mbase = (w >> 2) * 64, nbase = (w & 3) * 32;
    const int k2r = tid >> 4, sg = (tid & 15) * 16;
    const __half* Ag = g_E2 + ((size_t)(b * (LCc / 2) + k2r) * LQq + q0) * 2 + sg;
    const __half* Bg = g_C2 + ((size_t)(k2r * NB + b) * ND + d0) * 2 + sg;
    const u32 Ad = smem_u32(&As[0][k2r][sg]);
    const u32 Bd = smem_u32(&Bs[0][k2r][sg]);
    cpa16(Ad, Ag); cpa16(Ad + 16, Ag + 8);
    cpa16(Bd, Bg); cpa16(Bd + 16, Bg + 8);
    cpa_commit();
    float4 acc[4][4] = {};
    for (int ch = 0; ch < 32; ++ch) {
        const int p = ch & 1;
        if (ch < 31) {
            const size_t ca = (size_t)(ch + 1) * 16;
            const u32 off = (u32)((p ^ 1) * 8704);
            cpa16(Ad + off, Ag + ca * (LQq * 2));
            cpa16(Ad + off + 16, Ag + ca * (LQq * 2) + 8);
            cpa16(Bd + off, Bg + ca * ((size_t)NB * ND * 2));
            cpa16(Bd + off + 16, Bg + ca * ((size_t)NB * ND * 2) + 8);
            cpa_commit();
            cpa_wait<1>();
        } else cpa_wait<0>();
        __syncthreads();
#pragma unroll
        for (int s = 0; s < 2; ++s) {
            u32 af[4][4], bf[4][2];
#pragma unroll
            for (int mi = 0; mi < 4; ++mi) {
                int m = mbase + mi * 16 + g;
                af[mi][0] = *(const u32*)&As[p][8 * s + t][2 * m];
                af[mi][1] = *(const u32*)&As[p][8 * s + t][2 * (m + 8)];
                af[mi][2] = *(const u32*)&As[p][8 * s + t + 4][2 * m];
                af[mi][3] = *(const u32*)&As[p][8 * s + t + 4][2 * (m + 8)];
            }
#pragma unroll
            for (int ni = 0; ni < 4; ++ni) {
                int n = nbase + ni * 8 + g;
                bf[ni][0] = *(const u32*)&Bs[p][8 * s + t][2 * n];
                bf[ni][1] = *(const u32*)&Bs[p][8 * s + t + 4][2 * n];
            }
#pragma unroll
            for (int mi = 0; mi < 4; ++mi)
#pragma unroll
                for (int ni = 0; ni < 4; ++ni)
                    mma16(acc[mi][ni], af[mi][0], af[mi][1], af[mi][2], af[mi][3],
                          bf[ni][0], bf[ni][1]);
        }
        __syncthreads();
    }
#pragma unroll
    for (int mi = 0; mi < 4; ++mi) {
        int qA = q0 + mbase + mi * 16 + g;
        float i0 = 1.0f / g_csum2[b * LQq + qA];
        float i1 = 1.0f / g_csum2[b * LQq + qA + 8];
        // FIX vs R10: include d0 in the M2 base offset
        size_t m0b = ((size_t)(b * (LQq / 2) + (qA >> 1)) * ND + d0) * 2 + (qA & 1);
        size_t m1b = m0b + (size_t)8 * ND;
#pragma unroll
        for (int ni = 0; ni < 4; ++ni) {
            int d = nbase + ni * 8 + 2 * t;
            g_M2[m0b + 2 * d]     = h_rn(acc[mi][ni].x * i0);
            g_M2[m0b + 2 * d + 2] = h_rn(acc[mi][ni].y * i0);
            g_M2[m1b + 2 * d]     = h_rn(acc[mi][ni].z * i1);
            g_M2[m1b + 2 * d + 2] = h_rn(acc[mi][ni].w * i1);
        }
    }
}

// ---- k5: A = S1@Q, B_ = S1@M; A=g_Eh, Bq=g_Q2, Bm=g_M2; transposed concat ------
__global__ __launch_bounds__(256, 2) void k5_out(const float* __restrict__ C,
                                                 float* __restrict__ out) {
    __shared__ __align__(16) char sm5[38912];
    __half (*As)[128][40] = (__half(*)[128][40])sm5;              // 2*10240
    __half (*Bq)[16][144] = (__half(*)[16][144])(sm5 + 20480);    // 2*4608
    __half (*Bm)[16][144] = (__half(*)[16][144])(sm5 + 29696);    // 2*4608
    float (*Cs)[65]       = (float(*)[65])sm5;                    // epilogue 16640
    float (*Tr)[69]       = (float(*)[69])(sm5 + 16640);          // epilogue 17664
    const int b = blockIdx.z, c0 = blockIdx.y * 128, d0 = blockIdx.x * 64;
    const int tid = threadIdx.x, lane = tid & 31, w = tid >> 5;
    const int g = lane >> 2, t = lane & 3;
    const int wr = w >> 1, wc = w & 1;
    const int mbase = wr * 32, nbase = wc * 32;
    const int rowc = tid >> 1, sgA = (tid & 1) * 16;
    const int k2r = tid >> 4, sgB = (tid & 15) * 8;
    const __half* Ag = g_Eh + (size_t)(b * LCc + c0 + rowc) * LQq + sgA;
    const __half* Qg = g_Q2 + ((size_t)(k2r * NB + b) * ND + d0) * 2 + sgB;
    const __half* Mg = g_M2 + ((size_t)(b * (LQq / 2) + k2r) * ND + d0) * 2 + sgB;
    const u32 Ad  = smem_u32(&As[0][rowc][sgA]);
    const u32 Bqd = smem_u32(&Bq[0][k2r][sgB]);
    const u32 Bmd = smem_u32(&Bm[0][k2r][sgB]);
    cpa16(Ad, Ag); cpa16(Ad + 16, Ag + 8);
    cpa16(Bqd, Qg); cpa16(Bmd, Mg);
    cpa_commit();
    float4 accA[2][4] = {}, accB[2][4] = {};
    for (int ch = 0; ch < 16; ++ch) {
        const int p = ch & 1;
        if (ch < 15) {
            const int ko = (ch + 1) * 32;
            const u32 offA = (u32)((p ^ 1) * 10240);
            const u32 offB = (u32)((p ^ 1) * 4608);
            cpa16(Ad + offA, Ag + ko); cpa16(Ad + offA + 16, Ag + ko + 8);
            cpa16(Bqd + offB, Qg + (size_t)(ch + 1) * 16 * ((size_t)NB * ND * 2));
            cpa16(Bmd + offB, Mg + (size_t)(ch + 1) * 16 * (ND * 2));
            cpa_commit();
            cpa_wait<1>();
        } else cpa_wait<0>();
        __syncthreads();
#pragma unroll
        for (int s = 0; s < 2; ++s) {
            u32 af[2][4], qf[4][2], mf[4][2];
#pragma unroll
            for (int mi = 0; mi < 2; ++mi) {
                int m = mbase + mi * 16 + g;
                af[mi][0] = *(const u32*)&As[p][m][16 * s + 2 * t];
                af[mi][1] = *(const u32*)&As[p][m + 8][16 * s + 2 * t];
                af[mi][2] = *(const u32*)&As[p][m][16 * s + 2 * t + 8];
                af[mi][3] = *(const u32*)&As[p][m + 8][16 * s + 2 * t + 8];
            }
#pragma unroll
            for (int ni = 0; ni < 4; ++ni) {
                int n = nbase + ni * 8 + g;
                qf[ni][0] = *(const u32*)&Bq[p][8 * s + t][2 * n];
                qf[ni][1] = *(const u32*)&Bq[p][8 * s + t + 4][2 * n];
                mf[ni][0] = *(const u32*)&Bm[p][8 * s + t][2 * n];
                mf[ni][1] = *(const u32*)&Bm[p][8 * s + t + 4][2 * n];
            }
#pragma unroll
            for (int mi = 0; mi < 2; ++mi)
#pragma unroll
                for (int ni = 0; ni < 4; ++ni) {
                    mma16(accA[mi][ni], af[mi][0], af[mi][1], af[mi][2], af[mi][3],
                          qf[ni][0], qf[ni][1]);
                    mma16(accB[mi][ni], af[mi][0], af[mi][1], af[mi][2], af[mi][3],
                          mf[ni][0], mf[ni][1]);
                }
        }
        __syncthreads();
    }
#pragma unroll
    for (int mi = 0; mi < 2; ++mi) {
        int cA = c0 + mbase + mi * 16 + g;
        float i0 = g_invrs[b * LCc + cA];
        float i1 = g_invrs[b * LCc + cA + 8];
#pragma unroll
        for (int ni = 0; ni < 4; ++ni) {
            accA[mi][ni].x *= i0; accA[mi][ni].y *= i0;
            accA[mi][ni].z *= i1; accA[mi][ni].w *= i1;
            accB[mi][ni].x *= i0; accB[mi][ni].y *= i0;
            accB[mi][ni].z *= i1; accB[mi][ni].w *= i1;
        }
    }
    const int cl = tid & 63, dseg = (tid >> 6) * 16;
    const int cr = tid & 63, db = tid >> 6;
    const size_t ob = (size_t)b * (4 * ND) * LCc;
    for (int h = 0; h < 2; ++h) {
        __syncthreads();
        {
            const float* Cg = C + (size_t)(c0 + h * 64 + cl) * (NB * ND) + (size_t)b * ND + d0 + dseg;
#pragma unroll
            for (int dd = 0; dd < 16; dd += 4) {
                float4 cv = *(const float4*)(Cg + dd);
                Cs[dseg + dd + 0][cl] = cv.x; Cs[dseg + dd + 1][cl] = cv.y;
                Cs[dseg + dd + 2][cl] = cv.z; Cs[dseg + dd + 3][cl] = cv.w;
            }
        }
        if ((w >> 2) == h) {
#pragma unroll
            for (int mi = 0; mi < 2; ++mi) {
                int clh = (wr & 1) * 32 + mi * 16 + g;
#pragma unroll
                for (int ni = 0; ni < 4; ++ni) {
                    int d = nbase + ni * 8 + 2 * t;
                    Tr[clh][d] = accA[mi][ni].x;     Tr[clh][d + 1] = accA[mi][ni].y;
                    Tr[clh + 8][d] = accA[mi][ni].z; Tr[clh + 8][d + 1] = accA[mi][ni].w;
                }
            }
        }
        __syncthreads();
#pragma unroll
        for (int rr = 0; rr < 16; ++rr) {
            int dr = db + rr * 4;
            float cval = Cs[dr][cr];
            float aval = Tr[cr][dr];
            size_t col = (size_t)(c0 + h * 64 + cr);
            out[ob + (size_t)(d0 + dr) * LCc + col]          = cval;
            out[ob + (size_t)(ND + d0 + dr) * LCc + col]     = aval;
            out[ob + (size_t)(2 * ND + d0 + dr) * LCc + col] = cval * aval;
        }
        __syncthreads();
        if ((w >> 2) == h) {
#pragma unroll
            for (int mi = 0; mi < 2; ++mi) {
                int clh = (wr & 1) * 32 + mi * 16 + g;
#pragma unroll
                for (int ni = 0; ni < 4; ++ni) {
                    int d = nbase + ni * 8 + 2 * t;
                    Tr[clh][d] = accB[mi][ni].x;     Tr[clh][d + 1] = accB[mi][ni].y;
                    Tr[clh + 8][d] = accB[mi][ni].z; Tr[clh + 8][d + 1] = accB[mi][ni].w;
                }
            }
        }
        __syncthreads();
#pragma unroll
        for (int rr = 0; rr < 16; ++rr) {
            int dr = db + rr * 4;
            out[ob + (size_t)(3 * ND + d0 + dr) * LCc + (size_t)(c0 + h * 64 + cr)] =
                Cs[dr][cr] * Tr[cr][dr];
        }
    }
}

extern "C" void kernel_launch(void* const* d_in, const int* in_sizes, int n_in,
                              void* d_out, int out_size) {
    const float* C     = (const float*)d_in[0];
    const float* Q     = (const float*)d_in[1];
    const float* w4C   = (const float*)d_in[2];
    const float* w4Q   = (const float*)d_in[3];
    const float* w4mlu = (const float*)d_in[4];
    const float* bias  = (const float*)d_in[5];
    float* out = (float*)d_out;

    k_init<<<(NB * LCc + 255) / 256, 256>>>();
    k0_sub<<<(NB * LCc + NB * LQq) / 8, 256>>>(C, Q, w4C, w4Q);
    k0q<<<(LQq * NB * ND / 4 + 255) / 256, 256>>>(Q, w4mlu);
    k0c<<<(LCc * NB * ND / 4 + 255) / 256, 256>>>(C);
    k1_scores<<<dim3(LQq / 128, LCc / 128, NB), 256>>>(bias);
    k_fin<<<(NB * LCc + 255) / 256, 256>>>();
    k4_M<<<dim3(ND / 128, LQq / 128, NB), 256>>>();
    k5_out<<<dim3(ND / 64, LCc / 128, NB), 256>>>(C, out);
}

// round 13
// speedup vs baseline: 2.3297x; 1.0723x over previous
#include <cuda_runtime.h>
#include <cuda_fp16.h>
#include <math.h>

#define LCc 1024
#define LQq 512
#define NB  64
#define ND  256

typedef unsigned int u32;

// fp16 operand arrays (pair-interleaved copies for k-major consumers)
__device__ __half g_Ch [(size_t)LCc * NB * ND];   // [c][b][d]            (k1 A)
__device__ __half g_C2 [(size_t)LCc * NB * ND];   // [c/2][b][d][c&1]     (k4 B)
__device__ __half g_Qwh[(size_t)LQq * NB * ND];   // [q][b][d]  Q*wml     (k1 B)
__device__ __half g_Q2 [(size_t)LQq * NB * ND];   // [q/2][b][d][q&1]     (k5 Bq)
__device__ __half g_Eh [(size_t)NB * LCc * LQq];  // [b][c][q]            (k5 A)
__device__ __half g_E2 [(size_t)NB * LCc * LQq];  // [b][c/2][q][c&1]     (k4 A)
__device__ __half g_M2 [(size_t)NB * LQq * ND];   // [b][q/2][d][q&1]     (k5 Bm)
__device__ float g_sub0[NB * LCc];
__device__ float g_sub1[NB * LQq];
__device__ float g_rsum[NB * LCc];
__device__ float g_invrs[NB * LCc];
__device__ float g_csum2[NB * LQq];

// ---------------- helpers -----------------------------------------------------
__device__ __forceinline__ void mma16(float4& d,
        u32 a0, u32 a1, u32 a2, u32 a3, u32 b0, u32 b1) {
    asm volatile("mma.sync.aligned.m16n8k16.row.col.f32.f16.f16.f32 "
        "{%0,%1,%2,%3}, {%4,%5,%6,%7}, {%8,%9}, {%0,%1,%2,%3};"
        : "+f"(d.x), "+f"(d.y), "+f"(d.z), "+f"(d.w)
        : "r"(a0), "r"(a1), "r"(a2), "r"(a3), "r"(b0), "r"(b1));
}
__device__ __forceinline__ u32 smem_u32(const void* p) {
    u32 a; asm("{ .reg .u64 t; cvta.to.shared.u64 t, %1; cvt.u32.u64 %0, t; }"
               : "=r"(a) : "l"(p));
    return a;
}
__device__ __forceinline__ void cpa16(u32 dst, const void* src) {
    asm volatile("cp.async.cg.shared.global [%0], [%1], 16;" :: "r"(dst), "l"(src) : "memory");
}
__device__ __forceinline__ void cpa_commit() {
    asm volatile("cp.async.commit_group;" ::: "memory");
}
template<int N>
__device__ __forceinline__ void cpa_wait() {
    asm volatile("cp.async.wait_group %0;" :: "n"(N) : "memory");
}
__device__ __forceinline__ __half h_rn(float f) { return __float2half_rn(f); }
// exp2 via FMA-pipe polynomial (no MUFU). Input e = x*log2(e); |e| <= ~14 here.
// rel err ~5e-7 (deg-5 Taylor on |f|<=0.5).
__device__ __forceinline__ float exp2p(float e) {
    float r = rintf(e);
    float f = e - r;
    float p = 1.33335581464e-3f;
    p = fmaf(p, f, 9.61812910763e-3f);
    p = fmaf(p, f, 5.55041086648e-2f);
    p = fmaf(p, f, 2.40226506959e-1f);
    p = fmaf(p, f, 6.93147180560e-1f);
    p = fmaf(p, f, 1.0f);
    int ei = (int)r;
    return p * __int_as_float((ei + 127) << 23);
}
#define L2E 1.44269504088896340736f

// ---------------- small kernels ------------------------------------------------
__global__ void k_init() {
    int i = blockIdx.x * blockDim.x + threadIdx.x;
    if (i < NB * LQq) g_csum2[i] = 0.f;
    if (i < NB * LCc) g_rsum[i] = 0.f;
}
__global__ void k_fin() {
    int i = blockIdx.x * blockDim.x + threadIdx.x;
    if (i < NB * LCc) g_invrs[i] = 1.0f / g_rsum[i];
}

__global__ __launch_bounds__(256) void k0_sub(const float* __restrict__ C,
                                              const float* __restrict__ Q,
                                              const float* __restrict__ w4C,
                                              const float* __restrict__ w4Q) {
    int gw   = (blockIdx.x * blockDim.x + threadIdx.x) >> 5;
    int lane = threadIdx.x & 31;
    const float* src; const float* w; float* dst;
    if (gw < NB * LCc) {
        src = C + (size_t)gw * ND; w = w4C;
        int c = gw / NB, b = gw % NB;
        dst = g_sub0 + b * LCc + c;
    } else {
        int r = gw - NB * LCc;
        if (r >= NB * LQq) return;
        src = Q + (size_t)r * ND; w = w4Q;
        int q = r / NB, b = r % NB;
        dst = g_sub1 + b * LQq + q;
    }
    float acc = 0.f;
    const float4* s4 = (const float4*)src;
    const float4* w4 = (const float4*)w;
#pragma unroll
    for (int j = 0; j < 2; ++j) {
        float4 a = s4[lane + 32 * j], ww = w4[lane + 32 * j];
        acc += a.x * ww.x + a.y * ww.y + a.z * ww.z + a.w * ww.w;
    }
#pragma unroll
    for (int off = 16; off; off >>= 1) acc += __shfl_xor_sync(0xffffffffu, acc, off);
    if (lane == 0) *dst = acc;
}

// Q pair-coalesced: thread handles (2qp, 2qp+1) x 4 d values
__global__ __launch_bounds__(256) void k0q(const float* __restrict__ Q,
                                           const float* __restrict__ wml) {
    int i = blockIdx.x * blockDim.x + threadIdx.x;
    if (i >= (LQq / 2) * NB * (ND / 4)) return;
    int d  = (i & 63) * 4;
    int b  = (i >> 6) & 63;
    int qp = i >> 12;
    float4 ww = ((const float4*)wml)[i & 63];
    float4 v0 = *(const float4*)(Q + ((size_t)(2 * qp)     * NB + b) * ND + d);
    float4 v1 = *(const float4*)(Q + ((size_t)(2 * qp + 1) * NB + b) * ND + d);
    // Qwh rows (scaled by wml)
    __half2* w0 = (__half2*)(g_Qwh + ((size_t)(2 * qp)     * NB + b) * ND + d);
    __half2* w1 = (__half2*)(g_Qwh + ((size_t)(2 * qp + 1) * NB + b) * ND + d);
    w0[0] = __floats2half2_rn(v0.x * ww.x, v0.y * ww.y);
    w0[1] = __floats2half2_rn(v0.z * ww.z, v0.w * ww.w);
    w1[0] = __floats2half2_rn(v1.x * ww.x, v1.y * ww.y);
    w1[1] = __floats2half2_rn(v1.z * ww.z, v1.w * ww.w);
    // Q2 interleaved: [qp][b][d][2], 16B contiguous per thread
    __half2* q2 = (__half2*)(g_Q2 + (((size_t)qp * NB + b) * ND + d) * 2);
    q2[0] = __floats2half2_rn(v0.x, v1.x);
    q2[1] = __floats2half2_rn(v0.y, v1.y);
    q2[2] = __floats2half2_rn(v0.z, v1.z);
    q2[3] = __floats2half2_rn(v0.w, v1.w);
}
// C pair-coalesced: thread handles (2cp, 2cp+1) x 4 d values
__global__ __launch_bounds__(256) void k0c(const float* __restrict__ C) {
    int i = blockIdx.x * blockDim.x + threadIdx.x;
    if (i >= (LCc / 2) * NB * (ND / 4)) return;
    int d  = (i & 63) * 4;
    int b  = (i >> 6) & 63;
    int cp = i >> 12;
    float4 v0 = *(const float4*)(C + ((size_t)(2 * cp)     * NB + b) * ND + d);
    float4 v1 = *(const float4*)(C + ((size_t)(2 * cp + 1) * NB + b) * ND + d);
    __half2* c0 = (__half2*)(g_Ch + ((size_t)(2 * cp)     * NB + b) * ND + d);
    __half2* c1 = (__half2*)(g_Ch + ((size_t)(2 * cp + 1) * NB + b) * ND + d);
    c0[0] = __floats2half2_rn(v0.x, v0.y);
    c0[1] = __floats2half2_rn(v0.z, v0.w);
    c1[0] = __floats2half2_rn(v1.x, v1.y);
    c1[1] = __floats2half2_rn(v1.z, v1.w);
    __half2* c2 = (__half2*)(g_C2 + (((size_t)cp * NB + b) * ND + d) * 2);
    c2[0] = __floats2half2_rn(v0.x, v1.x);
    c2[1] = __floats2half2_rn(v0.y, v1.y);
    c2[2] = __floats2half2_rn(v0.z, v1.z);
    c2[3] = __floats2half2_rn(v0.w, v1.w);
}

// ---- k1: E = exp(Ch @ Qwh^T + sub0 + sub1 + bias) -> g_Eh + g_E2; fused sums --
__global__ __launch_bounds__(256, 2) void k1_scores(const float* __restrict__ bias) {
    __shared__ __half As[2][128][40];
    __shared__ __half Bs[2][128][40];
    const int tid = threadIdx.x, lane = tid & 31, w = tid >> 5;
    const int g = lane >> 2, t = lane & 3;
    const int b = blockIdx.z, c0 = blockIdx.y * 128, q0 = blockIdx.x * 128;
    const int mbase = (w >> 2) * 64, nbase = (w & 3) * 32;
    const int row = tid >> 1, sg = (tid & 1) * 16;
    const __half* Ag = g_Ch + ((size_t)(c0 + row) * NB + b) * ND + sg;
    const __half* Bg = g_Qwh + ((size_t)(q0 + row) * NB + b) * ND + sg;
    const u32 Ad = smem_u32(&As[0][row][sg]);
    const u32 Bd = smem_u32(&Bs[0][row][sg]);
    cpa16(Ad, Ag); cpa16(Ad + 16, Ag + 8);
    cpa16(Bd, Bg); cpa16(Bd + 16, Bg + 8);
    cpa_commit();
    float4 acc[4][4] = {};
    for (int ch = 0; ch < 8; ++ch) {
        const int p = ch & 1;
        if (ch < 7) {
            const int ko = (ch + 1) * 32;
            const u32 off = (u32)((p ^ 1) * 10240);
            cpa16(Ad + off, Ag + ko); cpa16(Ad + off + 16, Ag + ko + 8);
            cpa16(Bd + off, Bg + ko); cpa16(Bd + off + 16, Bg + ko + 8);
            cpa_commit();
            cpa_wait<1>();
        } else cpa_wait<0>();
        __syncthreads();
#pragma unroll
        for (int kk = 0; kk < 32; kk += 16) {
            u32 af[4][4], bf[4][2];
#pragma unroll
            for (int mi = 0; mi < 4; ++mi) {
                int m = mbase + mi * 16 + g;
                af[mi][0] = *(const u32*)&As[p][m][kk + 2 * t];
                af[mi][1] = *(const u32*)&As[p][m + 8][kk + 2 * t];
                af[mi][2] = *(const u32*)&As[p][m][kk + 2 * t + 8];
                af[mi][3] = *(const u32*)&As[p][m + 8][kk + 2 * t + 8];
            }
#pragma unroll
            for (int ni = 0; ni < 4; ++ni) {
                int n = nbase + ni * 8 + g;
                bf[ni][0] = *(const u32*)&Bs[p][n][kk + 2 * t];
                bf[ni][1] = *(const u32*)&Bs[p][n][kk + 2 * t + 8];
            }
#pragma unroll
            for (int mi = 0; mi < 4; ++mi)
#pragma unroll
                for (int ni = 0; ni < 4; ++ni)
                    mma16(acc[mi][ni], af[mi][0], af[mi][1], af[mi][2], af[mi][3],
                          bf[ni][0], bf[ni][1]);
        }
        __syncthreads();
    }
    const float bv = bias[0];
    float s1x[4], s1y[4];
#pragma unroll
    for (int ni = 0; ni < 4; ++ni) {
        int q = q0 + nbase + ni * 8 + 2 * t;
        s1x[ni] = g_sub1[b * LQq + q] * L2E;
        s1y[ni] = g_sub1[b * LQq + q + 1] * L2E;
    }
    float rs0[4] = {}, rs1[4] = {}, ccx[4] = {}, ccy[4] = {};
#pragma unroll
    for (int mi = 0; mi < 4; ++mi) {
        int cA = c0 + mbase + mi * 16 + g;
        float s0a = (g_sub0[b * LCc + cA] + bv) * L2E;
        float s0b = (g_sub0[b * LCc + cA + 8] + bv) * L2E;
        __half* r0 = g_Eh + (size_t)(b * LCc + cA) * LQq + q0;
        __half* r1 = r0 + (size_t)8 * LQq;
        size_t e20 = ((size_t)(b * (LCc / 2) + (cA >> 1)) * LQq + q0) * 2 + (cA & 1);
        size_t e21 = e20 + (size_t)8 * LQq;
#pragma unroll
        for (int ni = 0; ni < 4; ++ni) {
            int q = nbase + ni * 8 + 2 * t;
            float f00 = exp2p(fmaf(acc[mi][ni].x, L2E, s0a + s1x[ni]));
            float f01 = exp2p(fmaf(acc[mi][ni].y, L2E, s0a + s1y[ni]));
            float f10 = exp2p(fmaf(acc[mi][ni].z, L2E, s0b + s1x[ni]));
            float f11 = exp2p(fmaf(acc[mi][ni].w, L2E, s0b + s1y[ni]));
            __half h00 = h_rn(f00), h01 = h_rn(f01);
            __half h10 = h_rn(f10), h11 = h_rn(f11);
            *(__half2*)(r0 + q) = __halves2half2(h00, h01);
            *(__half2*)(r1 + q) = __halves2half2(h10, h11);
            g_E2[e20 + 2 * q] = h00; g_E2[e20 + 2 * q + 2] = h01;
            g_E2[e21 + 2 * q] = h10; g_E2[e21 + 2 * q + 2] = h11;
            float v00 = __half2float(h00), v01 = __half2float(h01);
            float v10 = __half2float(h10), v11 = __half2float(h11);
            rs0[mi] += v00 + v01; rs1[mi] += v10 + v11;
            ccx[ni] += v00 + v10; ccy[ni] += v01 + v11;
        }
    }
#pragma unroll
    for (int mi = 0; mi < 4; ++mi) {
        float a = rs0[mi], c2 = rs1[mi];
        a  += __shfl_xor_sync(0xffffffffu, a, 1);  a  += __shfl_xor_sync(0xffffffffu, a, 2);
        c2 += __shfl_xor_sync(0xffffffffu, c2, 1); c2 += __shfl_xor_sync(0xffffffffu, c2, 2);
        if (t == 0) {
            int cA = c0 + mbase + mi * 16 + g;
            atomicAdd(&g_rsum[b * LCc + cA], a);
            atomicAdd(&g_rsum[b * LCc + cA + 8], c2);
        }
    }
#pragma unroll
    for (int ni = 0; ni < 4; ++ni) {
        float x = ccx[ni], y = ccy[ni];
        x += __shfl_xor_sync(0xffffffffu, x, 4);  y += __shfl_xor_sync(0xffffffffu, y, 4);
        x += __shfl_xor_sync(0xffffffffu, x, 8);  y += __shfl_xor_sync(0xffffffffu, y, 8);
        x += __shfl_xor_sync(0xffffffffu, x, 16); y += __shfl_xor_sync(0xffffffffu, y, 16);
        if (g == 0) {
            int q = q0 + nbase + ni * 8 + 2 * t;
            atomicAdd(&g_csum2[b * LQq + q], x);
            atomicAdd(&g_csum2[b * LQq + q + 1], y);
        }
    }
}

// ---- k4: M2 = (E^T @ C / colsum); A=g_E2, B=g_C2 -------------------------------
__global__ __launch_bounds__(256, 2) void k4_M() {
    __shared__ __half As[2][16][272];
    __shared__ __half Bs[2][16][272];
    const int b = blockIdx.z, q0 = blockIdx.y * 128, d0 = blockIdx.x * 128;
    const int tid = threadIdx.x, lane = tid & 31, w = tid >> 5;
    const int g = lane >> 2, t = lane & 3;
    const int mbase = (w >> 2) * 64, nbase = (w & 3) * 32;
    const int k2r = tid >> 4, sg = (tid & 15) * 16;
    const __half* Ag = g_E2 + ((size_t)(b * (LCc / 2) + k2r) * LQq + q0) * 2 + sg;
    const __half* Bg = g_C2 + ((size_t)(k2r * NB + b) * ND + d0) * 2 + sg;
    const u32 Ad = smem_u32(&As[0][k2r][sg]);
    const u32 Bd = smem_u32(&Bs[0][k2r][sg]);
    cpa16(Ad, Ag); cpa16(Ad + 16, Ag + 8);
    cpa16(Bd, Bg); cpa16(Bd + 16, Bg + 8);
    cpa_commit();
    float4 acc[4][4] = {};
    for (int ch = 0; ch < 32; ++ch) {
        const int p = ch & 1;
        if (ch < 31) {
            const size_t ca = (size_t)(ch + 1) * 16;
            const u32 off = (u32)((p ^ 1) * 8704);
            cpa16(Ad + off, Ag + ca * (LQq * 2));
            cpa16(Ad + off + 16, Ag + ca * (LQq * 2) + 8);
            cpa16(Bd + off, Bg + ca * ((size_t)NB * ND * 2));
            cpa16(Bd + off + 16, Bg + ca * ((size_t)NB * ND * 2) + 8);
            cpa_commit();
            cpa_wait<1>();
        } else cpa_wait<0>();
        __syncthreads();
#pragma unroll
        for (int s = 0; s < 2; ++s) {
            u32 af[4][4], bf[4][2];
#pragma unroll
            for (int mi = 0; mi < 4; ++mi) {
                int m = mbase + mi * 16 + g;
                af[mi][0] = *(const u32*)&As[p][8 * s + t][2 * m];
                af[mi][1] = *(const u32*)&As[p][8 * s + t][2 * (m + 8)];
                af[mi][2] = *(const u32*)&As[p][8 * s + t + 4][2 * m];
                af[mi][3] = *(const u32*)&As[p][8 * s + t + 4][2 * (m + 8)];
            }
#pragma unroll
            for (int ni = 0; ni < 4; ++ni) {
                int n = nbase + ni * 8 + g;
                bf[ni][0] = *(const u32*)&Bs[p][8 * s + t][2 * n];
                bf[ni][1] = *(const u32*)&Bs[p][8 * s + t + 4][2 * n];
            }
#pragma unroll
            for (int mi = 0; mi < 4; ++mi)
#pragma unroll
                for (int ni = 0; ni < 4; ++ni)
                    mma16(acc[mi][ni], af[mi][0], af[mi][1], af[mi][2], af[mi][3],
                          bf[ni][0], bf[ni][1]);
        }
        __syncthreads();
    }
#pragma unroll
    for (int mi = 0; mi < 4; ++mi) {
        int qA = q0 + mbase + mi * 16 + g;
        float i0 = 1.0f / g_csum2[b * LQq + qA];
        float i1 = 1.0f / g_csum2[b * LQq + qA + 8];
        size_t m0b = ((size_t)(b * (LQq / 2) + (qA >> 1)) * ND + d0) * 2 + (qA & 1);
        size_t m1b = m0b + (size_t)8 * ND;
#pragma unroll
        for (int ni = 0; ni < 4; ++ni) {
            int d = nbase + ni * 8 + 2 * t;
            g_M2[m0b + 2 * d]     = h_rn(acc[mi][ni].x * i0);
            g_M2[m0b + 2 * d + 2] = h_rn(acc[mi][ni].y * i0);
            g_M2[m1b + 2 * d]     = h_rn(acc[mi][ni].z * i1);
            g_M2[m1b + 2 * d + 2] = h_rn(acc[mi][ni].w * i1);
        }
    }
}

// ---- k5: A = S1@Q, B_ = S1@M; A=g_Eh, Bq=g_Q2, Bm=g_M2; transposed concat ------
__global__ __launch_bounds__(256, 2) void k5_out(const float* __restrict__ C,
                                                 float* __restrict__ out) {
    __shared__ __align__(16) char sm5[38912];
    __half (*As)[128][40] = (__half(*)[128][40])sm5;              // 2*10240
    __half (*Bq)[16][144] = (__half(*)[16][144])(sm5 + 20480);    // 2*4608
    __half (*Bm)[16][144] = (__half(*)[16][144])(sm5 + 29696);    // 2*4608
    float (*Cs)[65]       = (float(*)[65])sm5;                    // epilogue
    float (*Tr)[69]       = (float(*)[69])(sm5 + 16640);          // epilogue
    const int b = blockIdx.z, c0 = blockIdx.y * 128, d0 = blockIdx.x * 64;
    const int tid = threadIdx.x, lane = tid & 31, w = tid >> 5;
    const int g = lane >> 2, t = lane & 3;
    const int wr = w >> 1, wc = w & 1;
    const int mbase = wr * 32, nbase = wc * 32;
    const int rowc = tid >> 1, sgA = (tid & 1) * 16;
    const int k2r = tid >> 4, sgB = (tid & 15) * 8;
    const __half* Ag = g_Eh + (size_t)(b * LCc + c0 + rowc) * LQq + sgA;
    const __half* Qg = g_Q2 + ((size_t)(k2r * NB + b) * ND + d0) * 2 + sgB;
    const __half* Mg = g_M2 + ((size_t)(b * (LQq / 2) + k2r) * ND + d0) * 2 + sgB;
    const u32 Ad  = smem_u32(&As[0][rowc][sgA]);
    const u32 Bqd = smem_u32(&Bq[0][k2r][sgB]);
    const u32 Bmd = smem_u32(&Bm[0][k2r][sgB]);
    cpa16(Ad, Ag); cpa16(Ad + 16, Ag + 8);
    cpa16(Bqd, Qg); cpa16(Bmd, Mg);
    cpa_commit();
    float4 accA[2][4] = {}, accB[2][4] = {};
    for (int ch = 0; ch < 16; ++ch) {
        const int p = ch & 1;
        if (ch < 15) {
            const int ko = (ch + 1) * 32;
            const u32 offA = (u32)((p ^ 1) * 10240);
            const u32 offB = (u32)((p ^ 1) * 4608);
            cpa16(Ad + offA, Ag + ko); cpa16(Ad + offA + 16, Ag + ko + 8);
            cpa16(Bqd + offB, Qg + (size_t)(ch + 1) * 16 * ((size_t)NB * ND * 2));
            cpa16(Bmd + offB, Mg + (size_t)(ch + 1) * 16 * (ND * 2));
            cpa_commit();
            cpa_wait<1>();
        } else cpa_wait<0>();
        __syncthreads();
#pragma unroll
        for (int s = 0; s < 2; ++s) {
            u32 af[2][4], qf[4][2], mf[4][2];
#pragma unroll
            for (int mi = 0; mi < 2; ++mi) {
                int m = mbase + mi * 16 + g;
                af[mi][0] = *(const u32*)&As[p][m][16 * s + 2 * t];
                af[mi][1] = *(const u32*)&As[p][m + 8][16 * s + 2 * t];
                af[mi][2] = *(const u32*)&As[p][m][16 * s + 2 * t + 8];
                af[mi][3] = *(const u32*)&As[p][m + 8][16 * s + 2 * t + 8];
            }
#pragma unroll
            for (int ni = 0; ni < 4; ++ni) {
                int n = nbase + ni * 8 + g;
                qf[ni][0] = *(const u32*)&Bq[p][8 * s + t][2 * n];
                qf[ni][1] = *(const u32*)&Bq[p][8 * s + t + 4][2 * n];
                mf[ni][0] = *(const u32*)&Bm[p][8 * s + t][2 * n];
                mf[ni][1] = *(const u32*)&Bm[p][8 * s + t + 4][2 * n];
            }
#pragma unroll
            for (int mi = 0; mi < 2; ++mi)
#pragma unroll
                for (int ni = 0; ni < 4; ++ni) {
                    mma16(accA[mi][ni], af[mi][0], af[mi][1], af[mi][2], af[mi][3],
                          qf[ni][0], qf[ni][1]);
                    mma16(accB[mi][ni], af[mi][0], af[mi][1], af[mi][2], af[mi][3],
                          mf[ni][0], mf[ni][1]);
                }
        }
        __syncthreads();
    }
#pragma unroll
    for (int mi = 0; mi < 2; ++mi) {
        int cA = c0 + mbase + mi * 16 + g;
        float i0 = g_invrs[b * LCc + cA];
        float i1 = g_invrs[b * LCc + cA + 8];
#pragma unroll
        for (int ni = 0; ni < 4; ++ni) {
            accA[mi][ni].x *= i0; accA[mi][ni].y *= i0;
            accA[mi][ni].z *= i1; accA[mi][ni].w *= i1;
            accB[mi][ni].x *= i0; accB[mi][ni].y *= i0;
            accB[mi][ni].z *= i1; accB[mi][ni].w *= i1;
        }
    }
    const int cl = tid & 63, dseg = (tid >> 6) * 16;
    const int cr = tid & 63, db = tid >> 6;
    const size_t ob = (size_t)b * (4 * ND) * LCc;
    for (int h = 0; h < 2; ++h) {
        __syncthreads();
        {
            const float* Cg = C + (size_t)(c0 + h * 64 + cl) * (NB * ND) + (size_t)b * ND + d0 + dseg;
#pragma unroll
            for (int dd = 0; dd < 16; dd += 4) {
                float4 cv = *(const float4*)(Cg + dd);
                Cs[dseg + dd + 0][cl] = cv.x; Cs[dseg + dd + 1][cl] = cv.y;
                Cs[dseg + dd + 2][cl] = cv.z; Cs[dseg + dd + 3][cl] = cv.w;
            }
        }
        if ((w >> 2) == h) {
#pragma unroll
            for (int mi = 0; mi < 2; ++mi) {
                int clh = (wr & 1) * 32 + mi * 16 + g;
#pragma unroll
                for (int ni = 0; ni < 4; ++ni) {
                    int d = nbase + ni * 8 + 2 * t;
                    Tr[clh][d] = accA[mi][ni].x;     Tr[clh][d + 1] = accA[mi][ni].y;
                    Tr[clh + 8][d] = accA[mi][ni].z; Tr[clh + 8][d + 1] = accA[mi][ni].w;
                }
            }
        }
        __syncthreads();
#pragma unroll
        for (int rr = 0; rr < 16; ++rr) {
            int dr = db + rr * 4;
            float cval = Cs[dr][cr];
            float aval = Tr[cr][dr];
            size_t col = (size_t)(c0 + h * 64 + cr);
            out[ob + (size_t)(d0 + dr) * LCc + col]          = cval;
            out[ob + (size_t)(ND + d0 + dr) * LCc + col]     = aval;
            out[ob + (size_t)(2 * ND + d0 + dr) * LCc + col] = cval * aval;
        }
        __syncthreads();
        if ((w >> 2) == h) {
#pragma unroll
            for (int mi = 0; mi < 2; ++mi) {
                int clh = (wr & 1) * 32 + mi * 16 + g;
#pragma unroll
                for (int ni = 0; ni < 4; ++ni) {
                    int d = nbase + ni * 8 + 2 * t;
                    Tr[clh][d] = accB[mi][ni].x;     Tr[clh][d + 1] = accB[mi][ni].y;
                    Tr[clh + 8][d] = accB[mi][ni].z; Tr[clh + 8][d + 1] = accB[mi][ni].w;
                }
            }
        }
        __syncthreads();
#pragma unroll
        for (int rr = 0; rr < 16; ++rr) {
            int dr = db + rr * 4;
            out[ob + (size_t)(3 * ND + d0 + dr) * LCc + (size_t)(c0 + h * 64 + cr)] =
                Cs[dr][cr] * Tr[cr][dr];
        }
    }
}

extern "C" void kernel_launch(void* const* d_in, const int* in_sizes, int n_in,
                              void* d_out, int out_size) {
    const float* C     = (const float*)d_in[0];
    const float* Q     = (const float*)d_in[1];
    const float* w4C   = (const float*)d_in[2];
    const float* w4Q   = (const float*)d_in[3];
    const float* w4mlu = (const float*)d_in[4];
    const float* bias  = (const float*)d_in[5];
    float* out = (float*)d_out;

    k_init<<<(NB * LCc + 255) / 256, 256>>>();
    k0_sub<<<(NB * LCc + NB * LQq) / 8, 256>>>(C, Q, w4C, w4Q);
    k0q<<<(LQq / 2) * NB * (ND / 4) / 256, 256>>>(Q, w4mlu);
    k0c<<<(LCc / 2) * NB * (ND / 4) / 256, 256>>>(C);
    k1_scores<<<dim3(LQq / 128, LCc / 128, NB), 256>>>(bias);
    k_fin<<<(NB * LCc + 255) / 256, 256>>>();
    k4_M<<<dim3(ND / 128, LQq / 128, NB), 256>>>();
    k5_out<<<dim3(ND / 64, LCc / 128, NB), 256>>>(C, out);
}